// round 1
// baseline (speedup 1.0000x reference)
#include <cuda_runtime.h>
#include <cstdint>

// ---------------- problem constants (hardcoded from reference) ----------------
#define NQ_   900
#define B_    8
#define D_    256
#define H_    8
#define DH_   32
#define L_    4
#define P_    5
#define S_    21760
#define DFF_  1024
#define NTOK_ (NQ_ * B_)      // 7200
#define MTOK_ (S_ * B_)       // 174080

// level tables: shapes [[128,128],[64,64],[32,32],[16,16]], starts cumsum
__device__ __constant__ int c_Hl[4]    = {128, 64, 32, 16};
__device__ __constant__ int c_start[4] = {0, 16384, 20480, 21504};

// ---------------- scratch (device globals; no allocation in kernel_launch) ----
__device__ float g_q[B_*H_*NQ_*DH_];
__device__ float g_k[B_*H_*NQ_*DH_];
__device__ float g_v[B_*H_*NQ_*DH_];
__device__ float g_attn[NTOK_*D_];
__device__ float g_saproj[NTOK_*D_];
__device__ float g_tgt1[NTOK_*D_];
__device__ float g_value[B_*H_*S_*DH_];
__device__ float g_off[NTOK_*(H_*L_*P_*2)];
__device__ float g_aw[NTOK_*(H_*L_*P_)];
__device__ float g_ca[NTOK_*D_];
__device__ float g_caproj[NTOK_*D_];
__device__ float g_tgt2[NTOK_*D_];
__device__ float g_ffh[NTOK_*DFF_];
__device__ float g_ff[NTOK_*D_];

// ---------------- generic tiled GEMM: C = act(A @ W^T + bias) -----------------
// A: [M,K] row-major (AMODE==1: A = A0 + A1 elementwise)
// W: [N,K] row-major
// OMODE 0: C[r*N + n]
// OMODE 1: "heads" layout: r = s*8 + b  ->  C[((b*8 + n/32)*nrows + s)*32 + n%32]
template<int AMODE, int OMODE, bool RELU>
__global__ void gemm64(const float* __restrict__ A0, const float* __restrict__ A1,
                       const float* __restrict__ W,  const float* __restrict__ bias,
                       float* __restrict__ C, int M, int N, int K, int nrows)
{
    __shared__ float As[16][64];
    __shared__ float Bs[16][64];

    const int tid = threadIdx.x;
    const int ty  = tid >> 4;        // 0..15
    const int tx  = tid & 15;        // 0..15
    const int rowBase = blockIdx.x * 64;
    const int colBase = blockIdx.y * 64;

    const int la_row = tid >> 2;         // 0..63
    const int la_col = (tid & 3) << 2;   // 0,4,8,12

    float acc[4][4];
#pragma unroll
    for (int i = 0; i < 4; i++)
#pragma unroll
        for (int j = 0; j < 4; j++) acc[i][j] = 0.f;

    for (int k0 = 0; k0 < K; k0 += 16) {
        // load A tile (transposed into k-major smem)
        {
            int gr = rowBase + la_row;
            float4 av = make_float4(0.f, 0.f, 0.f, 0.f);
            if (gr < M) {
                av = *(const float4*)(A0 + (size_t)gr * K + k0 + la_col);
                if (AMODE == 1) {
                    float4 bv = *(const float4*)(A1 + (size_t)gr * K + k0 + la_col);
                    av.x += bv.x; av.y += bv.y; av.z += bv.z; av.w += bv.w;
                }
            }
            As[la_col + 0][la_row] = av.x;
            As[la_col + 1][la_row] = av.y;
            As[la_col + 2][la_row] = av.z;
            As[la_col + 3][la_row] = av.w;
        }
        // load W tile
        {
            int gn = colBase + la_row;
            float4 wv = make_float4(0.f, 0.f, 0.f, 0.f);
            if (gn < N) wv = *(const float4*)(W + (size_t)gn * K + k0 + la_col);
            Bs[la_col + 0][la_row] = wv.x;
            Bs[la_col + 1][la_row] = wv.y;
            Bs[la_col + 2][la_row] = wv.z;
            Bs[la_col + 3][la_row] = wv.w;
        }
        __syncthreads();

#pragma unroll
        for (int kk = 0; kk < 16; kk++) {
            float4 a = *(const float4*)&As[kk][ty * 4];
            float4 b = *(const float4*)&Bs[kk][tx * 4];
            float aa[4] = {a.x, a.y, a.z, a.w};
            float bb[4] = {b.x, b.y, b.z, b.w};
#pragma unroll
            for (int i = 0; i < 4; i++)
#pragma unroll
                for (int j = 0; j < 4; j++)
                    acc[i][j] = fmaf(aa[i], bb[j], acc[i][j]);
        }
        __syncthreads();
    }

#pragma unroll
    for (int i = 0; i < 4; i++) {
        int r = rowBase + ty * 4 + i;
        if (r >= M) continue;
#pragma unroll
        for (int j = 0; j < 4; j++) {
            int n = colBase + tx * 4 + j;
            if (n >= N) continue;
            float v = acc[i][j] + bias[n];
            if (RELU) v = fmaxf(v, 0.f);
            if (OMODE == 0) {
                C[(size_t)r * N + n] = v;
            } else {
                int s = r >> 3, bb2 = r & 7;
                C[(((size_t)(bb2 * 8 + (n >> 5))) * nrows + s) * 32 + (n & 31)] = v;
            }
        }
    }
}

// ---------------- flash self-attention: warp per query ------------------------
// q,k,v: [B*H][NQ][32]; out: token-major [q*B+b][256]
__global__ void attn_kernel(const float* __restrict__ q, const float* __restrict__ k,
                            const float* __restrict__ v, float* __restrict__ out)
{
    __shared__ float Ks[64][33];
    __shared__ float Vs[64][32];
    __shared__ float Qs[8][32];

    const int bh   = blockIdx.y;
    const int w    = threadIdx.x >> 5;
    const int lane = threadIdx.x & 31;
    const int qi   = blockIdx.x * 8 + w;
    const bool qv  = (qi < NQ_);

    if (qv) Qs[w][lane] = q[((size_t)bh * NQ_ + qi) * 32 + lane] * 0.17677669529663687f;
    __syncwarp();

    float m = -1e30f, l = 0.f, acc = 0.f;

    for (int kt = 0; kt < NQ_; kt += 64) {
        // cooperative tile load
        for (int i = threadIdx.x; i < 64 * 32; i += 256) {
            int kk = i >> 5, d = i & 31;
            int kg = kt + kk;
            float kv = 0.f, vv = 0.f;
            if (kg < NQ_) {
                kv = k[((size_t)bh * NQ_ + kg) * 32 + d];
                vv = v[((size_t)bh * NQ_ + kg) * 32 + d];
            }
            Ks[kk][d] = kv;
            Vs[kk][d] = vv;
        }
        __syncthreads();

        if (qv) {
            float d0 = 0.f, d1 = 0.f;
#pragma unroll
            for (int d = 0; d < 32; d++) {
                float qd = Qs[w][d];
                d0 = fmaf(qd, Ks[lane][d], d0);
                d1 = fmaf(qd, Ks[lane + 32][d], d1);
            }
            float s0 = (kt + lane      < NQ_) ? d0 : -1e30f;
            float s1 = (kt + lane + 32 < NQ_) ? d1 : -1e30f;

            float mn = fmaxf(s0, s1);
#pragma unroll
            for (int o = 16; o; o >>= 1) mn = fmaxf(mn, __shfl_xor_sync(0xffffffffu, mn, o));
            mn = fmaxf(m, mn);

            float scale = __expf(m - mn);
            float p0 = __expf(s0 - mn);
            float p1 = __expf(s1 - mn);
            float ps = p0 + p1;
#pragma unroll
            for (int o = 16; o; o >>= 1) ps += __shfl_xor_sync(0xffffffffu, ps, o);
            l = l * scale + ps;
            acc *= scale;
            m = mn;

#pragma unroll
            for (int j = 0; j < 32; j++) {
                float pj = __shfl_sync(0xffffffffu, p0, j);
                acc = fmaf(pj, Vs[j][lane], acc);
            }
#pragma unroll
            for (int j = 0; j < 32; j++) {
                float pj = __shfl_sync(0xffffffffu, p1, j);
                acc = fmaf(pj, Vs[j + 32][lane], acc);
            }
        }
        __syncthreads();
    }

    if (qv) {
        int b = bh >> 3, h = bh & 7;
        out[((size_t)qi * B_ + b) * D_ + h * 32 + lane] = acc / l;
    }
}

// ---------------- layer norm: out = LN(a + r) * g + be ------------------------
__global__ void ln_kernel(const float* __restrict__ a, const float* __restrict__ r,
                          const float* __restrict__ g, const float* __restrict__ be,
                          float* __restrict__ out)
{
    __shared__ float red[32];
    const int t = blockIdx.x, i = threadIdx.x;
    float x = a[(size_t)t * D_ + i] + r[(size_t)t * D_ + i];

    float s = x;
#pragma unroll
    for (int o = 16; o; o >>= 1) s += __shfl_xor_sync(0xffffffffu, s, o);
    if ((i & 31) == 0) red[i >> 5] = s;
    __syncthreads();
    if (i < 8) {
        float vv = red[i];
#pragma unroll
        for (int o = 4; o; o >>= 1) vv += __shfl_xor_sync(0xffu, vv, o);
        if (i == 0) red[0] = vv;
    }
    __syncthreads();
    float mean = red[0] * (1.f / 256.f);
    float d = x - mean;
    float s2 = d * d;
#pragma unroll
    for (int o = 16; o; o >>= 1) s2 += __shfl_xor_sync(0xffffffffu, s2, o);
    __syncthreads();
    if ((i & 31) == 0) red[i >> 5] = s2;
    __syncthreads();
    if (i < 8) {
        float vv = red[i];
#pragma unroll
        for (int o = 4; o; o >>= 1) vv += __shfl_xor_sync(0xffu, vv, o);
        if (i == 0) red[0] = vv;
    }
    __syncthreads();
    float var = red[0] * (1.f / 256.f);
    out[(size_t)t * D_ + i] = d * rsqrtf(var + 1e-5f) * g[i] + be[i];
}

// ---------------- deformable sampling: warp per (b,q,h), lane = channel -------
__global__ void sample_kernel(const float* __restrict__ off, const float* __restrict__ awl,
                              const float* __restrict__ refp, const float* __restrict__ val,
                              float* __restrict__ out)
{
    const int gw   = blockIdx.x * 8 + (threadIdx.x >> 5);
    const int lane = threadIdx.x & 31;
    const int t = gw >> 3;          // token = q*B + b
    const int h = gw & 7;
    const int b = t & 7;

    // softmax over 20 attention-weight logits per (t,h)
    float logit = (lane < 20) ? awl[(size_t)t * 160 + h * 20 + lane] : -1e30f;
    float mx = logit;
#pragma unroll
    for (int o = 16; o; o >>= 1) mx = fmaxf(mx, __shfl_xor_sync(0xffffffffu, mx, o));
    float e = (lane < 20) ? __expf(logit - mx) : 0.f;
    float sm = e;
#pragma unroll
    for (int o = 16; o; o >>= 1) sm += __shfl_xor_sync(0xffffffffu, sm, o);
    float pw = e / sm;

    const float* rp = refp + (size_t)t * 16;   // [L][4]
    const float* op = off + (size_t)t * 320 + h * 40;

    float acc = 0.f;
#pragma unroll
    for (int l = 0; l < 4; l++) {
        const int Wl = c_Hl[l];
        const int Hl = c_Hl[l];
        const float r0 = rp[l * 4 + 0], r1 = rp[l * 4 + 1];
        const float r2 = rp[l * 4 + 2], r3 = rp[l * 4 + 3];
        const float* vbase = val + ((size_t)(b * 8 + h) * S_ + c_start[l]) * 32;
#pragma unroll
        for (int p = 0; p < 5; p++) {
            float aw = __shfl_sync(0xffffffffu, pw, l * 5 + p);
            float ox = op[(l * 5 + p) * 2 + 0];
            float oy = op[(l * 5 + p) * 2 + 1];
            float x = (r0 + ox * 0.2f * r2 * 0.5f) * (float)Wl - 0.5f;
            float y = (r1 + oy * 0.2f * r3 * 0.5f) * (float)Hl - 0.5f;
            float x0f = floorf(x), y0f = floorf(y);
            float fx = x - x0f, fy = y - y0f;
            int x0 = (int)x0f, y0 = (int)y0f;
#pragma unroll
            for (int dy = 0; dy < 2; dy++) {
#pragma unroll
                for (int dx = 0; dx < 2; dx++) {
                    int xi = x0 + dx, yi = y0 + dy;
                    float w = (dx ? fx : 1.f - fx) * (dy ? fy : 1.f - fy);
                    bool valid = (xi >= 0) && (xi < Wl) && (yi >= 0) && (yi < Hl);
                    if (valid && w != 0.f)
                        acc = fmaf(aw * w, vbase[((size_t)yi * Wl + xi) * 32 + lane], acc);
                }
            }
        }
    }
    out[(size_t)t * D_ + h * 32 + lane] = acc;
}

// ---------------- host launcher -----------------------------------------------
static inline int cdiv(int a, int b) { return (a + b - 1) / b; }

extern "C" void kernel_launch(void* const* d_in, const int* in_sizes, int n_in,
                              void* d_out, int out_size)
{
    const float* tgt     = (const float*)d_in[0];
    const float* pos     = (const float*)d_in[1];
    const float* refp    = (const float*)d_in[2];
    const float* memory  = (const float*)d_in[3];
    const float* sa_in_w = (const float*)d_in[4];
    const float* sa_in_b = (const float*)d_in[5];
    const float* sa_out_w= (const float*)d_in[6];
    const float* sa_out_b= (const float*)d_in[7];
    const float* off_w   = (const float*)d_in[8];
    const float* off_b   = (const float*)d_in[9];
    const float* aw_w    = (const float*)d_in[10];
    const float* aw_b    = (const float*)d_in[11];
    const float* val_w   = (const float*)d_in[12];
    const float* val_b   = (const float*)d_in[13];
    const float* co_w    = (const float*)d_in[14];
    const float* co_b    = (const float*)d_in[15];
    const float* w1      = (const float*)d_in[16];
    const float* b1      = (const float*)d_in[17];
    const float* w2      = (const float*)d_in[18];
    const float* b2      = (const float*)d_in[19];
    const float* ln1_g   = (const float*)d_in[20];
    const float* ln1_b   = (const float*)d_in[21];
    const float* ln2_g   = (const float*)d_in[22];
    const float* ln2_b   = (const float*)d_in[23];
    const float* ln3_g   = (const float*)d_in[24];
    const float* ln3_b   = (const float*)d_in[25];
    float* out = (float*)d_out;

    void *p;
    cudaGetSymbolAddress(&p, g_q);      float* q_     = (float*)p;
    cudaGetSymbolAddress(&p, g_k);      float* k_     = (float*)p;
    cudaGetSymbolAddress(&p, g_v);      float* v_     = (float*)p;
    cudaGetSymbolAddress(&p, g_attn);   float* attn_  = (float*)p;
    cudaGetSymbolAddress(&p, g_saproj); float* sap_   = (float*)p;
    cudaGetSymbolAddress(&p, g_tgt1);   float* tgt1_  = (float*)p;
    cudaGetSymbolAddress(&p, g_value);  float* value_ = (float*)p;
    cudaGetSymbolAddress(&p, g_off);    float* off_   = (float*)p;
    cudaGetSymbolAddress(&p, g_aw);     float* aw_    = (float*)p;
    cudaGetSymbolAddress(&p, g_ca);     float* ca_    = (float*)p;
    cudaGetSymbolAddress(&p, g_caproj); float* cap_   = (float*)p;
    cudaGetSymbolAddress(&p, g_tgt2);   float* tgt2_  = (float*)p;
    cudaGetSymbolAddress(&p, g_ffh);    float* ffh_   = (float*)p;
    cudaGetSymbolAddress(&p, g_ff);     float* ff_    = (float*)p;

    const dim3 blk(256);

    // ---- self-attention ----
    // q/k: (tgt + pos) @ Wq/Wk^T ; v: tgt @ Wv^T  -> [B*H][NQ][32]
    {
        dim3 grid(cdiv(NTOK_, 64), cdiv(D_, 64));
        gemm64<1, 1, false><<<grid, blk>>>(tgt, pos, sa_in_w,            sa_in_b,       q_, NTOK_, D_, D_, NQ_);
        gemm64<1, 1, false><<<grid, blk>>>(tgt, pos, sa_in_w + 256*256,  sa_in_b + 256, k_, NTOK_, D_, D_, NQ_);
        gemm64<0, 1, false><<<grid, blk>>>(tgt, pos, sa_in_w + 512*256,  sa_in_b + 512, v_, NTOK_, D_, D_, NQ_);
    }
    attn_kernel<<<dim3(cdiv(NQ_, 8), B_ * H_), blk>>>(q_, k_, v_, attn_);
    {
        dim3 grid(cdiv(NTOK_, 64), cdiv(D_, 64));
        gemm64<0, 0, false><<<grid, blk>>>(attn_, nullptr, sa_out_w, sa_out_b, sap_, NTOK_, D_, D_, 0);
    }
    ln_kernel<<<NTOK_, blk>>>(tgt, sap_, ln2_g, ln2_b, tgt1_);

    // ---- deformable cross-attention ----
    {   // value projection -> [B*H][S][32]
        dim3 grid(cdiv(MTOK_, 64), cdiv(D_, 64));
        gemm64<0, 1, false><<<grid, blk>>>(memory, nullptr, val_w, val_b, value_, MTOK_, D_, D_, S_);
    }
    {   // offsets & attention-weight logits from (tgt1 + pos)
        dim3 go(cdiv(NTOK_, 64), cdiv(320, 64));
        gemm64<1, 0, false><<<go, blk>>>(tgt1_, pos, off_w, off_b, off_, NTOK_, 320, D_, 0);
        dim3 ga(cdiv(NTOK_, 64), cdiv(160, 64));
        gemm64<1, 0, false><<<ga, blk>>>(tgt1_, pos, aw_w, aw_b, aw_, NTOK_, 160, D_, 0);
    }
    sample_kernel<<<NTOK_ * H_ / 8, blk>>>(off_, aw_, refp, value_, ca_);
    {
        dim3 grid(cdiv(NTOK_, 64), cdiv(D_, 64));
        gemm64<0, 0, false><<<grid, blk>>>(ca_, nullptr, co_w, co_b, cap_, NTOK_, D_, D_, 0);
    }
    ln_kernel<<<NTOK_, blk>>>(tgt1_, cap_, ln1_g, ln1_b, tgt2_);

    // ---- FFN ----
    {
        dim3 g1(cdiv(NTOK_, 64), cdiv(DFF_, 64));
        gemm64<0, 0, true ><<<g1, blk>>>(tgt2_, nullptr, w1, b1, ffh_, NTOK_, DFF_, D_, 0);
        dim3 g2(cdiv(NTOK_, 64), cdiv(D_, 64));
        gemm64<0, 0, false><<<g2, blk>>>(ffh_, nullptr, w2, b2, ff_, NTOK_, D_, DFF_, 0);
    }
    ln_kernel<<<NTOK_, blk>>>(tgt2_, ff_, ln3_g, ln3_b, out);
}

// round 2
// speedup vs baseline: 1.2971x; 1.2971x over previous
#include <cuda_runtime.h>
#include <cstdint>

// ---------------- problem constants (hardcoded from reference) ----------------
#define NQ_   900
#define B_    8
#define D_    256
#define H_    8
#define DH_   32
#define L_    4
#define P_    5
#define S_    21760
#define DFF_  1024
#define NTOK_ (NQ_ * B_)      // 7200
#define MTOK_ (S_ * B_)       // 174080

// level tables: shapes [[128,128],[64,64],[32,32],[16,16]], starts cumsum
__device__ __constant__ int c_Hl[4]    = {128, 64, 32, 16};
__device__ __constant__ int c_start[4] = {0, 16384, 20480, 21504};

// ---------------- scratch (device globals; no allocation in kernel_launch) ----
__device__ float g_q[B_*H_*NQ_*DH_];
__device__ float g_k[B_*H_*NQ_*DH_];
__device__ float g_v[B_*H_*NQ_*DH_];
__device__ float g_attn[NTOK_*D_];
__device__ float g_saproj[NTOK_*D_];
__device__ float g_tgt1[NTOK_*D_];
__device__ float g_value[B_*H_*S_*DH_];
__device__ float g_off[NTOK_*(H_*L_*P_*2)];
__device__ float g_aw[NTOK_*(H_*L_*P_)];
__device__ float g_ca[NTOK_*D_];
__device__ float g_caproj[NTOK_*D_];
__device__ float g_tgt2[NTOK_*D_];
__device__ float g_ffh[NTOK_*DFF_];
__device__ float g_ff[NTOK_*D_];

// ---------------- generic tiled GEMM: C = act(A @ W^T + bias) -----------------
// A: [M,K] row-major (AMODE==1: A = A0 + A1 elementwise)
// W: [N,K] row-major
// OMODE 0: C[r*N + n]
// OMODE 1: "heads" layout: r = s*8 + b  ->  C[((b*8 + n/32)*nrows + s)*32 + n%32]
template<int AMODE, int OMODE, bool RELU>
__global__ void gemm64(const float* __restrict__ A0, const float* __restrict__ A1,
                       const float* __restrict__ W,  const float* __restrict__ bias,
                       float* __restrict__ C, int M, int N, int K, int nrows)
{
    __shared__ float As[16][64];
    __shared__ float Bs[16][64];

    const int tid = threadIdx.x;
    const int ty  = tid >> 4;        // 0..15
    const int tx  = tid & 15;        // 0..15
    const int rowBase = blockIdx.x * 64;
    const int colBase = blockIdx.y * 64;

    const int la_row = tid >> 2;         // 0..63
    const int la_col = (tid & 3) << 2;   // 0,4,8,12

    float acc[4][4];
#pragma unroll
    for (int i = 0; i < 4; i++)
#pragma unroll
        for (int j = 0; j < 4; j++) acc[i][j] = 0.f;

    for (int k0 = 0; k0 < K; k0 += 16) {
        // load A tile (transposed into k-major smem)
        {
            int gr = rowBase + la_row;
            float4 av = make_float4(0.f, 0.f, 0.f, 0.f);
            if (gr < M) {
                av = *(const float4*)(A0 + (size_t)gr * K + k0 + la_col);
                if (AMODE == 1) {
                    float4 bv = *(const float4*)(A1 + (size_t)gr * K + k0 + la_col);
                    av.x += bv.x; av.y += bv.y; av.z += bv.z; av.w += bv.w;
                }
            }
            As[la_col + 0][la_row] = av.x;
            As[la_col + 1][la_row] = av.y;
            As[la_col + 2][la_row] = av.z;
            As[la_col + 3][la_row] = av.w;
        }
        // load W tile
        {
            int gn = colBase + la_row;
            float4 wv = make_float4(0.f, 0.f, 0.f, 0.f);
            if (gn < N) wv = *(const float4*)(W + (size_t)gn * K + k0 + la_col);
            Bs[la_col + 0][la_row] = wv.x;
            Bs[la_col + 1][la_row] = wv.y;
            Bs[la_col + 2][la_row] = wv.z;
            Bs[la_col + 3][la_row] = wv.w;
        }
        __syncthreads();

#pragma unroll
        for (int kk = 0; kk < 16; kk++) {
            float4 a = *(const float4*)&As[kk][ty * 4];
            float4 b = *(const float4*)&Bs[kk][tx * 4];
            float aa[4] = {a.x, a.y, a.z, a.w};
            float bb[4] = {b.x, b.y, b.z, b.w};
#pragma unroll
            for (int i = 0; i < 4; i++)
#pragma unroll
                for (int j = 0; j < 4; j++)
                    acc[i][j] = fmaf(aa[i], bb[j], acc[i][j]);
        }
        __syncthreads();
    }

#pragma unroll
    for (int i = 0; i < 4; i++) {
        int r = rowBase + ty * 4 + i;
        if (r >= M) continue;
#pragma unroll
        for (int j = 0; j < 4; j++) {
            int n = colBase + tx * 4 + j;
            if (n >= N) continue;
            float v = acc[i][j] + bias[n];
            if (RELU) v = fmaxf(v, 0.f);
            if (OMODE == 0) {
                C[(size_t)r * N + n] = v;
            } else {
                int s = r >> 3, bb2 = r & 7;
                C[(((size_t)(bb2 * 8 + (n >> 5))) * nrows + s) * 32 + (n & 31)] = v;
            }
        }
    }
}

// ---------------- GEMM-style flash self-attention ----------------------------
// Block: (64-query tile) x (bh). 256 threads.
// q,k,v: [B*H][NQ][32]; out token-major [q*B+b][256]
__global__ void attn_kernel(const float* __restrict__ q, const float* __restrict__ k,
                            const float* __restrict__ v, float* __restrict__ out)
{
    __shared__ float Qs[32][68];   // k-major Q^T (scaled)
    __shared__ float Ks[32][68];   // k-major K^T
    __shared__ float Vs[64][36];   // row-major V
    __shared__ float Ps[64][68];   // P^T: Ps[kk][r]

    const int bh  = blockIdx.y;
    const int q0  = blockIdx.x * 64;
    const int tid = threadIdx.x;
    const int ty  = tid >> 4;      // 0..15 : row group (4 rows)
    const int tx  = tid & 15;      // 0..15 : col group

    const float scale = 0.17677669529663687f;  // 1/sqrt(32)

    // load Q tile (scaled) into k-major smem
    for (int idx = tid; idx < 64 * 32; idx += 256) {
        int qq = idx >> 5, d = idx & 31;
        int gq = q0 + qq;
        Qs[d][qq] = (gq < NQ_) ? q[((size_t)bh * NQ_ + gq) * 32 + d] * scale : 0.f;
    }

    float m[4], l[4], o0[4], o1[4];
#pragma unroll
    for (int i = 0; i < 4; i++) { m[i] = -1e30f; l[i] = 0.f; o0[i] = 0.f; o1[i] = 0.f; }

    for (int kt = 0; kt < NQ_; kt += 64) {
        __syncthreads();   // protect Ks/Vs/Ps from previous iteration readers; also fences Qs on first pass

        // load K (k-major) and V (row-major) tiles
        for (int idx = tid; idx < 64 * 32; idx += 256) {
            int kk = idx >> 5, d = idx & 31;
            int kg = kt + kk;
            float kv = 0.f, vv = 0.f;
            if (kg < NQ_) {
                kv = k[((size_t)bh * NQ_ + kg) * 32 + d];
                vv = v[((size_t)bh * NQ_ + kg) * 32 + d];
            }
            Ks[d][kk] = kv;
            Vs[kk][d] = vv;
        }
        __syncthreads();

        // S = Q @ K^T  (4x4 register tile per thread)
        float sacc[4][4];
#pragma unroll
        for (int i = 0; i < 4; i++)
#pragma unroll
            for (int j = 0; j < 4; j++) sacc[i][j] = 0.f;

#pragma unroll
        for (int d = 0; d < 32; d++) {
            float4 a = *(const float4*)&Qs[d][ty * 4];
            float4 b = *(const float4*)&Ks[d][tx * 4];
            float aa[4] = {a.x, a.y, a.z, a.w};
            float bb[4] = {b.x, b.y, b.z, b.w};
#pragma unroll
            for (int i = 0; i < 4; i++)
#pragma unroll
                for (int j = 0; j < 4; j++)
                    sacc[i][j] = fmaf(aa[i], bb[j], sacc[i][j]);
        }

        // mask invalid keys
#pragma unroll
        for (int j = 0; j < 4; j++) {
            if (kt + tx * 4 + j >= NQ_) {
#pragma unroll
                for (int i = 0; i < 4; i++) sacc[i][j] = -1e30f;
            }
        }

        // online softmax per row (rows owned by the 16 threads sharing ty)
#pragma unroll
        for (int i = 0; i < 4; i++) {
            float mr = fmaxf(fmaxf(sacc[i][0], sacc[i][1]), fmaxf(sacc[i][2], sacc[i][3]));
#pragma unroll
            for (int off = 8; off; off >>= 1)
                mr = fmaxf(mr, __shfl_xor_sync(0xffffffffu, mr, off));
            float newm = fmaxf(m[i], mr);
            float corr = __expf(m[i] - newm);
            float p0v = __expf(sacc[i][0] - newm);
            float p1v = __expf(sacc[i][1] - newm);
            float p2v = __expf(sacc[i][2] - newm);
            float p3v = __expf(sacc[i][3] - newm);
            float rs = p0v + p1v + p2v + p3v;
#pragma unroll
            for (int off = 8; off; off >>= 1)
                rs += __shfl_xor_sync(0xffffffffu, rs, off);
            l[i] = l[i] * corr + rs;
            m[i] = newm;
            o0[i] *= corr;
            o1[i] *= corr;
            Ps[tx * 4 + 0][ty * 4 + i] = p0v;
            Ps[tx * 4 + 1][ty * 4 + i] = p1v;
            Ps[tx * 4 + 2][ty * 4 + i] = p2v;
            Ps[tx * 4 + 3][ty * 4 + i] = p3v;
        }
        __syncthreads();

        // O += P @ V : rows ty*4+i, cols tx*2 + {0,1}
#pragma unroll 8
        for (int kk = 0; kk < 64; kk++) {
            float4 pv = *(const float4*)&Ps[kk][ty * 4];
            float2 vv = *(const float2*)&Vs[kk][tx * 2];
            o0[0] = fmaf(pv.x, vv.x, o0[0]); o1[0] = fmaf(pv.x, vv.y, o1[0]);
            o0[1] = fmaf(pv.y, vv.x, o0[1]); o1[1] = fmaf(pv.y, vv.y, o1[1]);
            o0[2] = fmaf(pv.z, vv.x, o0[2]); o1[2] = fmaf(pv.z, vv.y, o1[2]);
            o0[3] = fmaf(pv.w, vv.x, o0[3]); o1[3] = fmaf(pv.w, vv.y, o1[3]);
        }
    }

    // write out: [q*B+b][h*32+d]
    const int b = bh >> 3, h = bh & 7;
#pragma unroll
    for (int i = 0; i < 4; i++) {
        int gq = q0 + ty * 4 + i;
        if (gq < NQ_) {
            float inv = 1.f / l[i];
            float* dst = out + ((size_t)gq * B_ + b) * D_ + h * 32 + tx * 2;
            dst[0] = o0[i] * inv;
            dst[1] = o1[i] * inv;
        }
    }
}

// ---------------- layer norm: out = LN(a + r) * g + be ------------------------
__global__ void ln_kernel(const float* __restrict__ a, const float* __restrict__ r,
                          const float* __restrict__ g, const float* __restrict__ be,
                          float* __restrict__ out)
{
    __shared__ float red[32];
    const int t = blockIdx.x, i = threadIdx.x;
    float x = a[(size_t)t * D_ + i] + r[(size_t)t * D_ + i];

    float s = x;
#pragma unroll
    for (int o = 16; o; o >>= 1) s += __shfl_xor_sync(0xffffffffu, s, o);
    if ((i & 31) == 0) red[i >> 5] = s;
    __syncthreads();
    if (i < 8) {
        float vv = red[i];
#pragma unroll
        for (int o = 4; o; o >>= 1) vv += __shfl_xor_sync(0xffu, vv, o);
        if (i == 0) red[0] = vv;
    }
    __syncthreads();
    float mean = red[0] * (1.f / 256.f);
    float d = x - mean;
    float s2 = d * d;
#pragma unroll
    for (int o = 16; o; o >>= 1) s2 += __shfl_xor_sync(0xffffffffu, s2, o);
    __syncthreads();
    if ((i & 31) == 0) red[i >> 5] = s2;
    __syncthreads();
    if (i < 8) {
        float vv = red[i];
#pragma unroll
        for (int o = 4; o; o >>= 1) vv += __shfl_xor_sync(0xffu, vv, o);
        if (i == 0) red[0] = vv;
    }
    __syncthreads();
    float var = red[0] * (1.f / 256.f);
    out[(size_t)t * D_ + i] = d * rsqrtf(var + 1e-5f) * g[i] + be[i];
}

// ---------------- deformable sampling: warp per (b,q,h), lane = channel -------
__global__ void sample_kernel(const float* __restrict__ off, const float* __restrict__ awl,
                              const float* __restrict__ refp, const float* __restrict__ val,
                              float* __restrict__ out)
{
    const int gw   = blockIdx.x * 8 + (threadIdx.x >> 5);
    const int lane = threadIdx.x & 31;
    const int t = gw >> 3;          // token = q*B + b
    const int h = gw & 7;
    const int b = t & 7;

    // softmax over 20 attention-weight logits per (t,h)
    float logit = (lane < 20) ? awl[(size_t)t * 160 + h * 20 + lane] : -1e30f;
    float mx = logit;
#pragma unroll
    for (int o = 16; o; o >>= 1) mx = fmaxf(mx, __shfl_xor_sync(0xffffffffu, mx, o));
    float e = (lane < 20) ? __expf(logit - mx) : 0.f;
    float sm = e;
#pragma unroll
    for (int o = 16; o; o >>= 1) sm += __shfl_xor_sync(0xffffffffu, sm, o);
    float pw = e / sm;

    const float* rp = refp + (size_t)t * 16;   // [L][4]
    const float* op = off + (size_t)t * 320 + h * 40;

    float acc = 0.f;
#pragma unroll
    for (int l = 0; l < 4; l++) {
        const int Wl = c_Hl[l];
        const int Hl = c_Hl[l];
        const float r0 = rp[l * 4 + 0], r1 = rp[l * 4 + 1];
        const float r2 = rp[l * 4 + 2], r3 = rp[l * 4 + 3];
        const float* vbase = val + ((size_t)(b * 8 + h) * S_ + c_start[l]) * 32;
#pragma unroll
        for (int p = 0; p < 5; p++) {
            float aw = __shfl_sync(0xffffffffu, pw, l * 5 + p);
            float ox = op[(l * 5 + p) * 2 + 0];
            float oy = op[(l * 5 + p) * 2 + 1];
            float x = (r0 + ox * 0.2f * r2 * 0.5f) * (float)Wl - 0.5f;
            float y = (r1 + oy * 0.2f * r3 * 0.5f) * (float)Hl - 0.5f;
            float x0f = floorf(x), y0f = floorf(y);
            float fx = x - x0f, fy = y - y0f;
            int x0 = (int)x0f, y0 = (int)y0f;
#pragma unroll
            for (int dy = 0; dy < 2; dy++) {
#pragma unroll
                for (int dx = 0; dx < 2; dx++) {
                    int xi = x0 + dx, yi = y0 + dy;
                    float w = (dx ? fx : 1.f - fx) * (dy ? fy : 1.f - fy);
                    bool valid = (xi >= 0) && (xi < Wl) && (yi >= 0) && (yi < Hl);
                    if (valid && w != 0.f)
                        acc = fmaf(aw * w, vbase[((size_t)yi * Wl + xi) * 32 + lane], acc);
                }
            }
        }
    }
    out[(size_t)t * D_ + h * 32 + lane] = acc;
}

// ---------------- host launcher -----------------------------------------------
static inline int cdiv(int a, int b) { return (a + b - 1) / b; }

extern "C" void kernel_launch(void* const* d_in, const int* in_sizes, int n_in,
                              void* d_out, int out_size)
{
    const float* tgt     = (const float*)d_in[0];
    const float* pos     = (const float*)d_in[1];
    const float* refp    = (const float*)d_in[2];
    const float* memory  = (const float*)d_in[3];
    const float* sa_in_w = (const float*)d_in[4];
    const float* sa_in_b = (const float*)d_in[5];
    const float* sa_out_w= (const float*)d_in[6];
    const float* sa_out_b= (const float*)d_in[7];
    const float* off_w   = (const float*)d_in[8];
    const float* off_b   = (const float*)d_in[9];
    const float* aw_w    = (const float*)d_in[10];
    const float* aw_b    = (const float*)d_in[11];
    const float* val_w   = (const float*)d_in[12];
    const float* val_b   = (const float*)d_in[13];
    const float* co_w    = (const float*)d_in[14];
    const float* co_b    = (const float*)d_in[15];
    const float* w1      = (const float*)d_in[16];
    const float* b1      = (const float*)d_in[17];
    const float* w2      = (const float*)d_in[18];
    const float* b2      = (const float*)d_in[19];
    const float* ln1_g   = (const float*)d_in[20];
    const float* ln1_b   = (const float*)d_in[21];
    const float* ln2_g   = (const float*)d_in[22];
    const float* ln2_b   = (const float*)d_in[23];
    const float* ln3_g   = (const float*)d_in[24];
    const float* ln3_b   = (const float*)d_in[25];
    float* out = (float*)d_out;

    void *p;
    cudaGetSymbolAddress(&p, g_q);      float* q_     = (float*)p;
    cudaGetSymbolAddress(&p, g_k);      float* k_     = (float*)p;
    cudaGetSymbolAddress(&p, g_v);      float* v_     = (float*)p;
    cudaGetSymbolAddress(&p, g_attn);   float* attn_  = (float*)p;
    cudaGetSymbolAddress(&p, g_saproj); float* sap_   = (float*)p;
    cudaGetSymbolAddress(&p, g_tgt1);   float* tgt1_  = (float*)p;
    cudaGetSymbolAddress(&p, g_value);  float* value_ = (float*)p;
    cudaGetSymbolAddress(&p, g_off);    float* off_   = (float*)p;
    cudaGetSymbolAddress(&p, g_aw);     float* aw_    = (float*)p;
    cudaGetSymbolAddress(&p, g_ca);     float* ca_    = (float*)p;
    cudaGetSymbolAddress(&p, g_caproj); float* cap_   = (float*)p;
    cudaGetSymbolAddress(&p, g_tgt2);   float* tgt2_  = (float*)p;
    cudaGetSymbolAddress(&p, g_ffh);    float* ffh_   = (float*)p;
    cudaGetSymbolAddress(&p, g_ff);     float* ff_    = (float*)p;

    const dim3 blk(256);

    // ---- self-attention ----
    // q/k: (tgt + pos) @ Wq/Wk^T ; v: tgt @ Wv^T  -> [B*H][NQ][32]
    {
        dim3 grid(cdiv(NTOK_, 64), cdiv(D_, 64));
        gemm64<1, 1, false><<<grid, blk>>>(tgt, pos, sa_in_w,            sa_in_b,       q_, NTOK_, D_, D_, NQ_);
        gemm64<1, 1, false><<<grid, blk>>>(tgt, pos, sa_in_w + 256*256,  sa_in_b + 256, k_, NTOK_, D_, D_, NQ_);
        gemm64<0, 1, false><<<grid, blk>>>(tgt, pos, sa_in_w + 512*256,  sa_in_b + 512, v_, NTOK_, D_, D_, NQ_);
    }
    attn_kernel<<<dim3(cdiv(NQ_, 64), B_ * H_), blk>>>(q_, k_, v_, attn_);
    {
        dim3 grid(cdiv(NTOK_, 64), cdiv(D_, 64));
        gemm64<0, 0, false><<<grid, blk>>>(attn_, nullptr, sa_out_w, sa_out_b, sap_, NTOK_, D_, D_, 0);
    }
    ln_kernel<<<NTOK_, blk>>>(tgt, sap_, ln2_g, ln2_b, tgt1_);

    // ---- deformable cross-attention ----
    {   // value projection -> [B*H][S][32]
        dim3 grid(cdiv(MTOK_, 64), cdiv(D_, 64));
        gemm64<0, 1, false><<<grid, blk>>>(memory, nullptr, val_w, val_b, value_, MTOK_, D_, D_, S_);
    }
    {   // offsets & attention-weight logits from (tgt1 + pos)
        dim3 go(cdiv(NTOK_, 64), cdiv(320, 64));
        gemm64<1, 0, false><<<go, blk>>>(tgt1_, pos, off_w, off_b, off_, NTOK_, 320, D_, 0);
        dim3 ga(cdiv(NTOK_, 64), cdiv(160, 64));
        gemm64<1, 0, false><<<ga, blk>>>(tgt1_, pos, aw_w, aw_b, aw_, NTOK_, 160, D_, 0);
    }
    sample_kernel<<<NTOK_ * H_ / 8, blk>>>(off_, aw_, refp, value_, ca_);
    {
        dim3 grid(cdiv(NTOK_, 64), cdiv(D_, 64));
        gemm64<0, 0, false><<<grid, blk>>>(ca_, nullptr, co_w, co_b, cap_, NTOK_, D_, D_, 0);
    }
    ln_kernel<<<NTOK_, blk>>>(tgt1_, cap_, ln1_g, ln1_b, tgt2_);

    // ---- FFN ----
    {
        dim3 g1(cdiv(NTOK_, 64), cdiv(DFF_, 64));
        gemm64<0, 0, true ><<<g1, blk>>>(tgt2_, nullptr, w1, b1, ffh_, NTOK_, DFF_, D_, 0);
        dim3 g2(cdiv(NTOK_, 64), cdiv(D_, 64));
        gemm64<0, 0, false><<<g2, blk>>>(ffh_, nullptr, w2, b2, ff_, NTOK_, D_, DFF_, 0);
    }
    ln_kernel<<<NTOK_, blk>>>(tgt2_, ff_, ln3_g, ln3_b, out);
}

// round 4
// speedup vs baseline: 2.3000x; 1.7732x over previous
#include <cuda_runtime.h>
#include <cuda_bf16.h>
#include <cstdint>

// ---------------- problem constants ----------------
#define NQ_   900
#define B_    8
#define D_    256
#define H_    8
#define DH_   32
#define L_    4
#define P_    5
#define S_    21760
#define DFF_  1024
#define NTOK_ (NQ_ * B_)      // 7200
#define MTOK_ (S_ * B_)       // 174080

__device__ __constant__ int c_Hl[4]    = {128, 64, 32, 16};
__device__ __constant__ int c_start[4] = {0, 16384, 20480, 21504};

// ---------------- scratch ----------------
__device__ float g_q[B_*H_*NQ_*DH_];
__device__ float g_k[B_*H_*NQ_*DH_];
__device__ float g_v[B_*H_*NQ_*DH_];
__device__ float g_attn[NTOK_*D_];
__device__ float g_saproj[NTOK_*D_];
__device__ float g_tgt1[NTOK_*D_];
__device__ float g_value[B_*H_*S_*DH_];
__device__ float g_off[NTOK_*(H_*L_*P_*2)];
__device__ float g_aw[NTOK_*(H_*L_*P_)];
__device__ float g_ca[NTOK_*D_];
__device__ float g_caproj[NTOK_*D_];
__device__ float g_tgt2[NTOK_*D_];
__device__ float g_ffh[NTOK_*DFF_];
__device__ float g_ff[NTOK_*D_];

// ================= mma.sync bf16 3-term fp32 GEMM =================
// C[M,N] = act(A[M,K] @ W[N,K]^T + bias).  fp32 emulated: a=hi+lo (bf16),
// D = Ahi*Bhi + Ahi*Blo + Alo*Bhi  (lo*lo dropped, ~2^-18 rel).
// CTA tile 128x64, 8 warps (warp tile 32x32), K chunk = 32 floats.
#define A_PITCH 80          // bytes per smem row (32 bf16 = 64B + 16B pad)
#define A_TILE  10240       // 128 * 80
#define B_TILE  5120        // 64  * 80
#define AOFF(bf, s) (((bf)*2 + (s)) * A_TILE)                 // hi=0, lo=1
#define BOFF(bf, s) (4*A_TILE + ((bf)*2 + (s)) * B_TILE)
#define SM_TOTAL (4*A_TILE + 4*B_TILE)                        // 61440

__device__ __forceinline__ uint32_t su32(const void* p) {
    uint32_t a;
    asm("{ .reg .u64 t; cvta.to.shared.u64 t, %1; cvt.u32.u64 %0, t; }" : "=r"(a) : "l"(p));
    return a;
}
__device__ __forceinline__ uint32_t pk(float a, float b) {
    __nv_bfloat162 h = __floats2bfloat162_rn(a, b);
    return reinterpret_cast<uint32_t&>(h);
}
__device__ __forceinline__ void ldsm4(uint32_t addr, uint32_t* r) {
    asm volatile("ldmatrix.sync.aligned.m8n8.x4.shared.b16 {%0,%1,%2,%3}, [%4];"
                 : "=r"(r[0]), "=r"(r[1]), "=r"(r[2]), "=r"(r[3]) : "r"(addr));
}
#define MMA16816(c, a, b0r, b1r) \
    asm volatile("mma.sync.aligned.m16n8k16.row.col.f32.bf16.bf16.f32 " \
                 "{%0,%1,%2,%3},{%4,%5,%6,%7},{%8,%9},{%0,%1,%2,%3};" \
                 : "+f"((c)[0]), "+f"((c)[1]), "+f"((c)[2]), "+f"((c)[3]) \
                 : "r"((a)[0]), "r"((a)[1]), "r"((a)[2]), "r"((a)[3]), \
                   "r"(b0r), "r"(b1r))

// OMODE 0: C[r*N+n]; OMODE 1: heads layout C[((b*8+n/32)*nrows + r/8)*32 + n%32]
template<int AMODE, int OMODE, bool RELU>
__global__ void __launch_bounds__(256) tgemm(
    const float* __restrict__ A0, const float* __restrict__ A1,
    const float* __restrict__ W,  const float* __restrict__ bias,
    float* __restrict__ C, int M, int N, int K, int nrows)
{
    extern __shared__ char sm[];
    const int tid  = threadIdx.x;
    const int lane = tid & 31;
    const int wid  = tid >> 5;
    const int wm   = wid & 3;       // row block (32 rows)
    const int wn   = wid >> 2;      // col block (32 cols)
    const int colBase = blockIdx.x * 64;
    const int rowBase = blockIdx.y * 128;

    const uint32_t smBase = su32(sm);

    // per-thread LDG -> smem mapping: idx -> (row = idx>>3, f4 = idx&7)
    float4 pa[4];   // A: 1024 float4 / 256 threads
    float4 pb[2];   // B: 512 float4 / 256 threads

    auto ldg_chunk = [&](int k0) {
#pragma unroll
        for (int i = 0; i < 4; i++) {
            int idx = tid + i * 256;
            int row = idx >> 3, f4 = idx & 7;
            int gr = rowBase + row;
            float4 v = make_float4(0.f, 0.f, 0.f, 0.f);
            if (gr < M) {
                v = *(const float4*)(A0 + (size_t)gr * K + k0 + f4 * 4);
                if (AMODE) {
                    float4 u = *(const float4*)(A1 + (size_t)gr * K + k0 + f4 * 4);
                    v.x += u.x; v.y += u.y; v.z += u.z; v.w += u.w;
                }
            }
            pa[i] = v;
        }
#pragma unroll
        for (int i = 0; i < 2; i++) {
            int idx = tid + i * 256;
            int row = idx >> 3, f4 = idx & 7;
            int gn = colBase + row;
            pb[i] = (gn < N) ? *(const float4*)(W + (size_t)gn * K + k0 + f4 * 4)
                             : make_float4(0.f, 0.f, 0.f, 0.f);
        }
    };

    auto sts_chunk = [&](int bf) {
#pragma unroll
        for (int i = 0; i < 4; i++) {
            int idx = tid + i * 256;
            int row = idx >> 3, f4 = idx & 7;
            float4 v = pa[i];
            float hx = __bfloat162float(__float2bfloat16_rn(v.x));
            float hy = __bfloat162float(__float2bfloat16_rn(v.y));
            float hz = __bfloat162float(__float2bfloat16_rn(v.z));
            float hw = __bfloat162float(__float2bfloat16_rn(v.w));
            uint2 Hi = make_uint2(pk(hx, hy), pk(hz, hw));
            uint2 Lo = make_uint2(pk(v.x - hx, v.y - hy), pk(v.z - hz, v.w - hw));
            *(uint2*)(sm + AOFF(bf, 0) + row * A_PITCH + f4 * 8) = Hi;
            *(uint2*)(sm + AOFF(bf, 1) + row * A_PITCH + f4 * 8) = Lo;
        }
#pragma unroll
        for (int i = 0; i < 2; i++) {
            int idx = tid + i * 256;
            int row = idx >> 3, f4 = idx & 7;
            float4 v = pb[i];
            float hx = __bfloat162float(__float2bfloat16_rn(v.x));
            float hy = __bfloat162float(__float2bfloat16_rn(v.y));
            float hz = __bfloat162float(__float2bfloat16_rn(v.z));
            float hw = __bfloat162float(__float2bfloat16_rn(v.w));
            uint2 Hi = make_uint2(pk(hx, hy), pk(hz, hw));
            uint2 Lo = make_uint2(pk(v.x - hx, v.y - hy), pk(v.z - hz, v.w - hw));
            *(uint2*)(sm + BOFF(bf, 0) + row * A_PITCH + f4 * 8) = Hi;
            *(uint2*)(sm + BOFF(bf, 1) + row * A_PITCH + f4 * 8) = Lo;
        }
    };

    float acc[2][4][4];
#pragma unroll
    for (int tm = 0; tm < 2; tm++)
#pragma unroll
        for (int tn = 0; tn < 4; tn++)
#pragma unroll
            for (int j = 0; j < 4; j++) acc[tm][tn][j] = 0.f;

    // ldmatrix lane addressing
    const int laneRow  = lane & 15;
    const int laneHalf = (lane & 16) ? 16 : 0;
    const uint32_t aRowOff  = (uint32_t)(wm * 32 + laneRow) * A_PITCH + laneHalf;
    const uint32_t bRowOff0 = (uint32_t)(wn * 32 + laneRow) * A_PITCH + laneHalf;
    const uint32_t bRowOff1 = (uint32_t)(wn * 32 + 16 + laneRow) * A_PITCH + laneHalf;

    const int NC = K >> 5;
    ldg_chunk(0);

    for (int c = 0; c < NC; c++) {
        int bf = c & 1;
        sts_chunk(bf);
        __syncthreads();
        if (c + 1 < NC) ldg_chunk((c + 1) * 32);

        const uint32_t aHiB = smBase + AOFF(bf, 0) + aRowOff;
        const uint32_t aLoB = smBase + AOFF(bf, 1) + aRowOff;
        const uint32_t bHiB0 = smBase + BOFF(bf, 0) + bRowOff0;
        const uint32_t bHiB1 = smBase + BOFF(bf, 0) + bRowOff1;
        const uint32_t bLoB0 = smBase + BOFF(bf, 1) + bRowOff0;
        const uint32_t bLoB1 = smBase + BOFF(bf, 1) + bRowOff1;

#pragma unroll
        for (int ks = 0; ks < 2; ks++) {
            uint32_t kof = ks * 32;
            uint32_t aH[2][4], aL[2][4], bH0[4], bH1[4], bL0[4], bL1[4];
            ldsm4(aHiB + kof,            aH[0]);
            ldsm4(aHiB + 16 * A_PITCH + kof, aH[1]);
            ldsm4(aLoB + kof,            aL[0]);
            ldsm4(aLoB + 16 * A_PITCH + kof, aL[1]);
            ldsm4(bHiB0 + kof, bH0);
            ldsm4(bHiB1 + kof, bH1);
            ldsm4(bLoB0 + kof, bL0);
            ldsm4(bLoB1 + kof, bL1);

            // n-tile tn: b0,b1 regs
            uint32_t b0h[4] = {bH0[0], bH0[1], bH1[0], bH1[1]};
            uint32_t b1h[4] = {bH0[2], bH0[3], bH1[2], bH1[3]};
            uint32_t b0l[4] = {bL0[0], bL0[1], bL1[0], bL1[1]};
            uint32_t b1l[4] = {bL0[2], bL0[3], bL1[2], bL1[3]};

#pragma unroll
            for (int tm = 0; tm < 2; tm++) {
#pragma unroll
                for (int tn = 0; tn < 4; tn++) {
                    MMA16816(acc[tm][tn], aH[tm], b0h[tn], b1h[tn]);   // hi*hi
                    MMA16816(acc[tm][tn], aH[tm], b0l[tn], b1l[tn]);   // hi*lo
                    MMA16816(acc[tm][tn], aL[tm], b0h[tn], b1h[tn]);   // lo*hi
                }
            }
        }
        __syncthreads();
    }

    // epilogue
    const int g  = lane >> 2;
    const int t4 = lane & 3;
#pragma unroll
    for (int tm = 0; tm < 2; tm++) {
        int row0 = rowBase + wm * 32 + tm * 16 + g;
#pragma unroll
        for (int tn = 0; tn < 4; tn++) {
            int col = colBase + wn * 32 + tn * 8 + t4 * 2;
            if (col >= N) continue;
            float b0 = bias[col], b1 = bias[col + 1];
            float* cc = acc[tm][tn];
            float v00 = cc[0] + b0, v01 = cc[1] + b1;
            float v10 = cc[2] + b0, v11 = cc[3] + b1;
            if (RELU) {
                v00 = fmaxf(v00, 0.f); v01 = fmaxf(v01, 0.f);
                v10 = fmaxf(v10, 0.f); v11 = fmaxf(v11, 0.f);
            }
            if (OMODE == 0) {
                if (row0 < M)     *(float2*)(C + (size_t)row0 * N + col)     = make_float2(v00, v01);
                if (row0 + 8 < M) *(float2*)(C + (size_t)(row0 + 8) * N + col) = make_float2(v10, v11);
            } else {
                int head = col >> 5, wi = col & 31;
                if (row0 < M) {
                    int s = row0 >> 3, bb = row0 & 7;
                    *(float2*)(C + (((size_t)(bb * 8 + head)) * nrows + s) * 32 + wi) = make_float2(v00, v01);
                }
                if (row0 + 8 < M) {
                    int r1 = row0 + 8;
                    int s = r1 >> 3, bb = r1 & 7;
                    *(float2*)(C + (((size_t)(bb * 8 + head)) * nrows + s) * 32 + wi) = make_float2(v10, v11);
                }
            }
        }
    }
}

// ---------------- GEMM-style flash self-attention ----------------------------
__global__ void attn_kernel(const float* __restrict__ q, const float* __restrict__ k,
                            const float* __restrict__ v, float* __restrict__ out)
{
    __shared__ float Qs[32][68];
    __shared__ float Ks[32][68];
    __shared__ float Vs[64][36];
    __shared__ float Ps[64][68];

    const int bh  = blockIdx.y;
    const int q0  = blockIdx.x * 64;
    const int tid = threadIdx.x;
    const int ty  = tid >> 4;
    const int tx  = tid & 15;

    const float scale = 0.17677669529663687f;

    for (int idx = tid; idx < 64 * 32; idx += 256) {
        int qq = idx >> 5, d = idx & 31;
        int gq = q0 + qq;
        Qs[d][qq] = (gq < NQ_) ? q[((size_t)bh * NQ_ + gq) * 32 + d] * scale : 0.f;
    }

    float m[4], l[4], o0[4], o1[4];
#pragma unroll
    for (int i = 0; i < 4; i++) { m[i] = -1e30f; l[i] = 0.f; o0[i] = 0.f; o1[i] = 0.f; }

    for (int kt = 0; kt < NQ_; kt += 64) {
        __syncthreads();
        for (int idx = tid; idx < 64 * 32; idx += 256) {
            int kk = idx >> 5, d = idx & 31;
            int kg = kt + kk;
            float kv = 0.f, vv = 0.f;
            if (kg < NQ_) {
                kv = k[((size_t)bh * NQ_ + kg) * 32 + d];
                vv = v[((size_t)bh * NQ_ + kg) * 32 + d];
            }
            Ks[d][kk] = kv;
            Vs[kk][d] = vv;
        }
        __syncthreads();

        float sacc[4][4];
#pragma unroll
        for (int i = 0; i < 4; i++)
#pragma unroll
            for (int j = 0; j < 4; j++) sacc[i][j] = 0.f;

#pragma unroll
        for (int d = 0; d < 32; d++) {
            float4 a = *(const float4*)&Qs[d][ty * 4];
            float4 b = *(const float4*)&Ks[d][tx * 4];
            float aa[4] = {a.x, a.y, a.z, a.w};
            float bb[4] = {b.x, b.y, b.z, b.w};
#pragma unroll
            for (int i = 0; i < 4; i++)
#pragma unroll
                for (int j = 0; j < 4; j++)
                    sacc[i][j] = fmaf(aa[i], bb[j], sacc[i][j]);
        }

#pragma unroll
        for (int j = 0; j < 4; j++) {
            if (kt + tx * 4 + j >= NQ_) {
#pragma unroll
                for (int i = 0; i < 4; i++) sacc[i][j] = -1e30f;
            }
        }

#pragma unroll
        for (int i = 0; i < 4; i++) {
            float mr = fmaxf(fmaxf(sacc[i][0], sacc[i][1]), fmaxf(sacc[i][2], sacc[i][3]));
#pragma unroll
            for (int off = 8; off; off >>= 1)
                mr = fmaxf(mr, __shfl_xor_sync(0xffffffffu, mr, off));
            float newm = fmaxf(m[i], mr);
            float corr = __expf(m[i] - newm);
            float p0v = __expf(sacc[i][0] - newm);
            float p1v = __expf(sacc[i][1] - newm);
            float p2v = __expf(sacc[i][2] - newm);
            float p3v = __expf(sacc[i][3] - newm);
            float rs = p0v + p1v + p2v + p3v;
#pragma unroll
            for (int off = 8; off; off >>= 1)
                rs += __shfl_xor_sync(0xffffffffu, rs, off);
            l[i] = l[i] * corr + rs;
            m[i] = newm;
            o0[i] *= corr;
            o1[i] *= corr;
            Ps[tx * 4 + 0][ty * 4 + i] = p0v;
            Ps[tx * 4 + 1][ty * 4 + i] = p1v;
            Ps[tx * 4 + 2][ty * 4 + i] = p2v;
            Ps[tx * 4 + 3][ty * 4 + i] = p3v;
        }
        __syncthreads();

#pragma unroll 8
        for (int kk = 0; kk < 64; kk++) {
            float4 pv = *(const float4*)&Ps[kk][ty * 4];
            float2 vv = *(const float2*)&Vs[kk][tx * 2];
            o0[0] = fmaf(pv.x, vv.x, o0[0]); o1[0] = fmaf(pv.x, vv.y, o1[0]);
            o0[1] = fmaf(pv.y, vv.x, o0[1]); o1[1] = fmaf(pv.y, vv.y, o1[1]);
            o0[2] = fmaf(pv.z, vv.x, o0[2]); o1[2] = fmaf(pv.z, vv.y, o1[2]);
            o0[3] = fmaf(pv.w, vv.x, o0[3]); o1[3] = fmaf(pv.w, vv.y, o1[3]);
        }
    }

    const int b = bh >> 3, h = bh & 7;
#pragma unroll
    for (int i = 0; i < 4; i++) {
        int gq = q0 + ty * 4 + i;
        if (gq < NQ_) {
            float inv = 1.f / l[i];
            float* dst = out + ((size_t)gq * B_ + b) * D_ + h * 32 + tx * 2;
            dst[0] = o0[i] * inv;
            dst[1] = o1[i] * inv;
        }
    }
}

// ---------------- layer norm ----------------
__global__ void ln_kernel(const float* __restrict__ a, const float* __restrict__ r,
                          const float* __restrict__ g, const float* __restrict__ be,
                          float* __restrict__ out)
{
    __shared__ float red[32];
    const int t = blockIdx.x, i = threadIdx.x;
    float x = a[(size_t)t * D_ + i] + r[(size_t)t * D_ + i];

    float s = x;
#pragma unroll
    for (int o = 16; o; o >>= 1) s += __shfl_xor_sync(0xffffffffu, s, o);
    if ((i & 31) == 0) red[i >> 5] = s;
    __syncthreads();
    if (i < 8) {
        float vv = red[i];
#pragma unroll
        for (int o = 4; o; o >>= 1) vv += __shfl_xor_sync(0xffu, vv, o);
        if (i == 0) red[0] = vv;
    }
    __syncthreads();
    float mean = red[0] * (1.f / 256.f);
    float d = x - mean;
    float s2 = d * d;
#pragma unroll
    for (int o = 16; o; o >>= 1) s2 += __shfl_xor_sync(0xffffffffu, s2, o);
    __syncthreads();
    if ((i & 31) == 0) red[i >> 5] = s2;
    __syncthreads();
    if (i < 8) {
        float vv = red[i];
#pragma unroll
        for (int o = 4; o; o >>= 1) vv += __shfl_xor_sync(0xffu, vv, o);
        if (i == 0) red[0] = vv;
    }
    __syncthreads();
    float var = red[0] * (1.f / 256.f);
    out[(size_t)t * D_ + i] = d * rsqrtf(var + 1e-5f) * g[i] + be[i];
}

// ---------------- deformable sampling ----------------
__global__ void sample_kernel(const float* __restrict__ off, const float* __restrict__ awl,
                              const float* __restrict__ refp, const float* __restrict__ val,
                              float* __restrict__ out)
{
    const int gw   = blockIdx.x * 8 + (threadIdx.x >> 5);
    const int lane = threadIdx.x & 31;
    const int t = gw >> 3;
    const int h = gw & 7;
    const int b = t & 7;

    float logit = (lane < 20) ? awl[(size_t)t * 160 + h * 20 + lane] : -1e30f;
    float mx = logit;
#pragma unroll
    for (int o = 16; o; o >>= 1) mx = fmaxf(mx, __shfl_xor_sync(0xffffffffu, mx, o));
    float e = (lane < 20) ? __expf(logit - mx) : 0.f;
    float sm = e;
#pragma unroll
    for (int o = 16; o; o >>= 1) sm += __shfl_xor_sync(0xffffffffu, sm, o);
    float pw = e / sm;

    const float* rp = refp + (size_t)t * 16;
    const float* op = off + (size_t)t * 320 + h * 40;

    float acc = 0.f;
#pragma unroll
    for (int l = 0; l < 4; l++) {
        const int Wl = c_Hl[l];
        const int Hl = c_Hl[l];
        const float r0 = rp[l * 4 + 0], r1 = rp[l * 4 + 1];
        const float r2 = rp[l * 4 + 2], r3 = rp[l * 4 + 3];
        const float* vbase = val + ((size_t)(b * 8 + h) * S_ + c_start[l]) * 32;
#pragma unroll
        for (int p = 0; p < 5; p++) {
            float aw = __shfl_sync(0xffffffffu, pw, l * 5 + p);
            float ox = op[(l * 5 + p) * 2 + 0];
            float oy = op[(l * 5 + p) * 2 + 1];
            float x = (r0 + ox * 0.2f * r2 * 0.5f) * (float)Wl - 0.5f;
            float y = (r1 + oy * 0.2f * r3 * 0.5f) * (float)Hl - 0.5f;
            float x0f = floorf(x), y0f = floorf(y);
            float fx = x - x0f, fy = y - y0f;
            int x0 = (int)x0f, y0 = (int)y0f;
#pragma unroll
            for (int dy = 0; dy < 2; dy++) {
#pragma unroll
                for (int dx = 0; dx < 2; dx++) {
                    int xi = x0 + dx, yi = y0 + dy;
                    float w = (dx ? fx : 1.f - fx) * (dy ? fy : 1.f - fy);
                    bool valid = (xi >= 0) && (xi < Wl) && (yi >= 0) && (yi < Hl);
                    if (valid && w != 0.f)
                        acc = fmaf(aw * w, vbase[((size_t)yi * Wl + xi) * 32 + lane], acc);
                }
            }
        }
    }
    out[(size_t)t * D_ + h * 32 + lane] = acc;
}

// ---------------- host launcher ----------------
static inline int cdiv(int a, int b) { return (a + b - 1) / b; }

extern "C" void kernel_launch(void* const* d_in, const int* in_sizes, int n_in,
                              void* d_out, int out_size)
{
    const float* tgt     = (const float*)d_in[0];
    const float* pos     = (const float*)d_in[1];
    const float* refp    = (const float*)d_in[2];
    const float* memory  = (const float*)d_in[3];
    const float* sa_in_w = (const float*)d_in[4];
    const float* sa_in_b = (const float*)d_in[5];
    const float* sa_out_w= (const float*)d_in[6];
    const float* sa_out_b= (const float*)d_in[7];
    const float* off_w   = (const float*)d_in[8];
    const float* off_b   = (const float*)d_in[9];
    const float* aw_w    = (const float*)d_in[10];
    const float* aw_b    = (const float*)d_in[11];
    const float* val_w   = (const float*)d_in[12];
    const float* val_b   = (const float*)d_in[13];
    const float* co_w    = (const float*)d_in[14];
    const float* co_b    = (const float*)d_in[15];
    const float* w1      = (const float*)d_in[16];
    const float* b1      = (const float*)d_in[17];
    const float* w2      = (const float*)d_in[18];
    const float* b2      = (const float*)d_in[19];
    const float* ln1_g   = (const float*)d_in[20];
    const float* ln1_b   = (const float*)d_in[21];
    const float* ln2_g   = (const float*)d_in[22];
    const float* ln2_b   = (const float*)d_in[23];
    const float* ln3_g   = (const float*)d_in[24];
    const float* ln3_b   = (const float*)d_in[25];
    float* out = (float*)d_out;

    void *p;
    cudaGetSymbolAddress(&p, g_q);      float* q_     = (float*)p;
    cudaGetSymbolAddress(&p, g_k);      float* k_     = (float*)p;
    cudaGetSymbolAddress(&p, g_v);      float* v_     = (float*)p;
    cudaGetSymbolAddress(&p, g_attn);   float* attn_  = (float*)p;
    cudaGetSymbolAddress(&p, g_saproj); float* sap_   = (float*)p;
    cudaGetSymbolAddress(&p, g_tgt1);   float* tgt1_  = (float*)p;
    cudaGetSymbolAddress(&p, g_value);  float* value_ = (float*)p;
    cudaGetSymbolAddress(&p, g_off);    float* off_   = (float*)p;
    cudaGetSymbolAddress(&p, g_aw);     float* aw_    = (float*)p;
    cudaGetSymbolAddress(&p, g_ca);     float* ca_    = (float*)p;
    cudaGetSymbolAddress(&p, g_caproj); float* cap_   = (float*)p;
    cudaGetSymbolAddress(&p, g_tgt2);   float* tgt2_  = (float*)p;
    cudaGetSymbolAddress(&p, g_ffh);    float* ffh_   = (float*)p;
    cudaGetSymbolAddress(&p, g_ff);     float* ff_    = (float*)p;

    static bool attr_done = false;
    if (!attr_done) {
        cudaFuncSetAttribute(tgemm<1,1,false>, cudaFuncAttributeMaxDynamicSharedMemorySize, SM_TOTAL);
        cudaFuncSetAttribute(tgemm<0,1,false>, cudaFuncAttributeMaxDynamicSharedMemorySize, SM_TOTAL);
        cudaFuncSetAttribute(tgemm<0,0,false>, cudaFuncAttributeMaxDynamicSharedMemorySize, SM_TOTAL);
        cudaFuncSetAttribute(tgemm<1,0,false>, cudaFuncAttributeMaxDynamicSharedMemorySize, SM_TOTAL);
        cudaFuncSetAttribute(tgemm<0,0,true >, cudaFuncAttributeMaxDynamicSharedMemorySize, SM_TOTAL);
        attr_done = true;
    }

    const dim3 blk(256);
    const int mt = cdiv(NTOK_, 128);   // 57

    // ---- self-attention ----
    tgemm<1,1,false><<<dim3(4, mt), 256, SM_TOTAL>>>(tgt, pos, sa_in_w,           sa_in_b,       q_, NTOK_, 256, 256, NQ_);
    tgemm<1,1,false><<<dim3(4, mt), 256, SM_TOTAL>>>(tgt, pos, sa_in_w + 256*256, sa_in_b + 256, k_, NTOK_, 256, 256, NQ_);
    tgemm<0,1,false><<<dim3(4, mt), 256, SM_TOTAL>>>(tgt, nullptr, sa_in_w + 512*256, sa_in_b + 512, v_, NTOK_, 256, 256, NQ_);
    attn_kernel<<<dim3(cdiv(NQ_, 64), B_ * H_), blk>>>(q_, k_, v_, attn_);
    tgemm<0,0,false><<<dim3(4, mt), 256, SM_TOTAL>>>(attn_, nullptr, sa_out_w, sa_out_b, sap_, NTOK_, 256, 256, 0);
    ln_kernel<<<NTOK_, blk>>>(tgt, sap_, ln2_g, ln2_b, tgt1_);

    // ---- deformable cross-attention ----
    tgemm<0,1,false><<<dim3(4, cdiv(MTOK_,128)), 256, SM_TOTAL>>>(memory, nullptr, val_w, val_b, value_, MTOK_, 256, 256, S_);
    tgemm<1,0,false><<<dim3(5, mt), 256, SM_TOTAL>>>(tgt1_, pos, off_w, off_b, off_, NTOK_, 320, 256, 0);
    tgemm<1,0,false><<<dim3(3, mt), 256, SM_TOTAL>>>(tgt1_, pos, aw_w, aw_b, aw_, NTOK_, 160, 256, 0);
    sample_kernel<<<NTOK_ * H_ / 8, blk>>>(off_, aw_, refp, value_, ca_);
    tgemm<0,0,false><<<dim3(4, mt), 256, SM_TOTAL>>>(ca_, nullptr, co_w, co_b, cap_, NTOK_, 256, 256, 0);
    ln_kernel<<<NTOK_, blk>>>(tgt1_, cap_, ln1_g, ln1_b, tgt2_);

    // ---- FFN ----
    tgemm<0,0,true ><<<dim3(16, mt), 256, SM_TOTAL>>>(tgt2_, nullptr, w1, b1, ffh_, NTOK_, DFF_, 256, 0);
    tgemm<0,0,false><<<dim3(4, mt), 256, SM_TOTAL>>>(ffh_, nullptr, w2, b2, ff_, NTOK_, 256, DFF_, 0);
    ln_kernel<<<NTOK_, blk>>>(tgt2_, ff_, ln3_g, ln3_b, out);
}

// round 5
// speedup vs baseline: 2.8158x; 1.2243x over previous
#include <cuda_runtime.h>
#include <cuda_bf16.h>
#include <cstdint>

// ---------------- problem constants ----------------
#define NQ_   900
#define NQP_  960            // padded keys (15 x 64)
#define B_    8
#define D_    256
#define H_    8
#define DH_   32
#define L_    4
#define P_    5
#define S_    21760
#define DFF_  1024
#define NTOK_ (NQ_ * B_)      // 7200
#define MTOK_ (S_ * B_)       // 174080

__device__ __constant__ int c_Hl[4]    = {128, 64, 32, 16};
__device__ __constant__ int c_start[4] = {0, 16384, 20480, 21504};

// ---------------- scratch ----------------
__device__ float g_q[B_*H_*NQ_*DH_];
__device__ float g_k[B_*H_*NQ_*DH_];
__device__ float g_v[B_*H_*NQ_*DH_];
__device__ __nv_bfloat16 g_kh[B_*H_*NQP_*DH_];
__device__ __nv_bfloat16 g_kl[B_*H_*NQP_*DH_];
__device__ __nv_bfloat16 g_vh[B_*H_*DH_*NQP_];   // transposed [bh][ch][key]
__device__ __nv_bfloat16 g_vl[B_*H_*DH_*NQP_];
__device__ float g_attn[NTOK_*D_];
__device__ float g_saproj[NTOK_*D_];
__device__ float g_tgt1[NTOK_*D_];
__device__ float g_value[B_*H_*S_*DH_];
__device__ float g_off[NTOK_*(H_*L_*P_*2)];
__device__ float g_aw[NTOK_*(H_*L_*P_)];
__device__ float g_ca[NTOK_*D_];
__device__ float g_caproj[NTOK_*D_];
__device__ float g_tgt2[NTOK_*D_];
__device__ float g_ffh[NTOK_*DFF_];
__device__ float g_ff[NTOK_*D_];

// ---------------- small helpers ----------------
__device__ __forceinline__ uint32_t su32(const void* p) {
    uint32_t a;
    asm("{ .reg .u64 t; cvta.to.shared.u64 t, %1; cvt.u32.u64 %0, t; }" : "=r"(a) : "l"(p));
    return a;
}
__device__ __forceinline__ uint32_t pk(float a, float b) {
    __nv_bfloat162 h = __floats2bfloat162_rn(a, b);
    return reinterpret_cast<uint32_t&>(h);
}
__device__ __forceinline__ void ldsm4(uint32_t addr, uint32_t* r) {
    asm volatile("ldmatrix.sync.aligned.m8n8.x4.shared.b16 {%0,%1,%2,%3}, [%4];"
                 : "=r"(r[0]), "=r"(r[1]), "=r"(r[2]), "=r"(r[3]) : "r"(addr));
}
#define MMA16816(c, a, b0r, b1r) \
    asm volatile("mma.sync.aligned.m16n8k16.row.col.f32.bf16.bf16.f32 " \
                 "{%0,%1,%2,%3},{%4,%5,%6,%7},{%8,%9},{%0,%1,%2,%3};" \
                 : "+f"((c)[0]), "+f"((c)[1]), "+f"((c)[2]), "+f"((c)[3]) \
                 : "r"((a)[0]), "r"((a)[1]), "r"((a)[2]), "r"((a)[3]), \
                   "r"(b0r), "r"(b1r))

// ================= mma.sync bf16 3-term fp32 GEMM =================
#define A_PITCH 80
#define A_TILE  10240
#define B_TILE  5120
#define AOFF(bf, s) (((bf)*2 + (s)) * A_TILE)
#define BOFF(bf, s) (4*A_TILE + ((bf)*2 + (s)) * B_TILE)
#define SM_TOTAL (4*A_TILE + 4*B_TILE)

template<int AMODE, int OMODE, bool RELU>
__global__ void __launch_bounds__(256) tgemm(
    const float* __restrict__ A0, const float* __restrict__ A1,
    const float* __restrict__ W,  const float* __restrict__ bias,
    float* __restrict__ C, int M, int N, int K, int nrows)
{
    extern __shared__ char sm[];
    const int tid  = threadIdx.x;
    const int lane = tid & 31;
    const int wid  = tid >> 5;
    const int wm   = wid & 3;
    const int wn   = wid >> 2;
    const int colBase = blockIdx.x * 64;
    const int rowBase = blockIdx.y * 128;

    const uint32_t smBase = su32(sm);

    float4 pa[4];
    float4 pb[2];

    auto ldg_chunk = [&](int k0) {
#pragma unroll
        for (int i = 0; i < 4; i++) {
            int idx = tid + i * 256;
            int row = idx >> 3, f4 = idx & 7;
            int gr = rowBase + row;
            float4 v = make_float4(0.f, 0.f, 0.f, 0.f);
            if (gr < M) {
                v = *(const float4*)(A0 + (size_t)gr * K + k0 + f4 * 4);
                if (AMODE) {
                    float4 u = *(const float4*)(A1 + (size_t)gr * K + k0 + f4 * 4);
                    v.x += u.x; v.y += u.y; v.z += u.z; v.w += u.w;
                }
            }
            pa[i] = v;
        }
#pragma unroll
        for (int i = 0; i < 2; i++) {
            int idx = tid + i * 256;
            int row = idx >> 3, f4 = idx & 7;
            int gn = colBase + row;
            pb[i] = (gn < N) ? *(const float4*)(W + (size_t)gn * K + k0 + f4 * 4)
                             : make_float4(0.f, 0.f, 0.f, 0.f);
        }
    };

    auto sts_chunk = [&](int bf) {
#pragma unroll
        for (int i = 0; i < 4; i++) {
            int idx = tid + i * 256;
            int row = idx >> 3, f4 = idx & 7;
            float4 v = pa[i];
            float hx = __bfloat162float(__float2bfloat16_rn(v.x));
            float hy = __bfloat162float(__float2bfloat16_rn(v.y));
            float hz = __bfloat162float(__float2bfloat16_rn(v.z));
            float hw = __bfloat162float(__float2bfloat16_rn(v.w));
            uint2 Hi = make_uint2(pk(hx, hy), pk(hz, hw));
            uint2 Lo = make_uint2(pk(v.x - hx, v.y - hy), pk(v.z - hz, v.w - hw));
            *(uint2*)(sm + AOFF(bf, 0) + row * A_PITCH + f4 * 8) = Hi;
            *(uint2*)(sm + AOFF(bf, 1) + row * A_PITCH + f4 * 8) = Lo;
        }
#pragma unroll
        for (int i = 0; i < 2; i++) {
            int idx = tid + i * 256;
            int row = idx >> 3, f4 = idx & 7;
            float4 v = pb[i];
            float hx = __bfloat162float(__float2bfloat16_rn(v.x));
            float hy = __bfloat162float(__float2bfloat16_rn(v.y));
            float hz = __bfloat162float(__float2bfloat16_rn(v.z));
            float hw = __bfloat162float(__float2bfloat16_rn(v.w));
            uint2 Hi = make_uint2(pk(hx, hy), pk(hz, hw));
            uint2 Lo = make_uint2(pk(v.x - hx, v.y - hy), pk(v.z - hz, v.w - hw));
            *(uint2*)(sm + BOFF(bf, 0) + row * A_PITCH + f4 * 8) = Hi;
            *(uint2*)(sm + BOFF(bf, 1) + row * A_PITCH + f4 * 8) = Lo;
        }
    };

    float acc[2][4][4];
#pragma unroll
    for (int tm = 0; tm < 2; tm++)
#pragma unroll
        for (int tn = 0; tn < 4; tn++)
#pragma unroll
            for (int j = 0; j < 4; j++) acc[tm][tn][j] = 0.f;

    const int laneRow  = lane & 15;
    const int laneHalf = (lane & 16) ? 16 : 0;
    const uint32_t aRowOff  = (uint32_t)(wm * 32 + laneRow) * A_PITCH + laneHalf;
    const uint32_t bRowOff0 = (uint32_t)(wn * 32 + laneRow) * A_PITCH + laneHalf;
    const uint32_t bRowOff1 = (uint32_t)(wn * 32 + 16 + laneRow) * A_PITCH + laneHalf;

    const int NC = K >> 5;
    ldg_chunk(0);

    for (int c = 0; c < NC; c++) {
        int bf = c & 1;
        sts_chunk(bf);
        __syncthreads();
        if (c + 1 < NC) ldg_chunk((c + 1) * 32);

        const uint32_t aHiB = smBase + AOFF(bf, 0) + aRowOff;
        const uint32_t aLoB = smBase + AOFF(bf, 1) + aRowOff;
        const uint32_t bHiB0 = smBase + BOFF(bf, 0) + bRowOff0;
        const uint32_t bHiB1 = smBase + BOFF(bf, 0) + bRowOff1;
        const uint32_t bLoB0 = smBase + BOFF(bf, 1) + bRowOff0;
        const uint32_t bLoB1 = smBase + BOFF(bf, 1) + bRowOff1;

#pragma unroll
        for (int ks = 0; ks < 2; ks++) {
            uint32_t kof = ks * 32;
            uint32_t aH[2][4], aL[2][4], bH0[4], bH1[4], bL0[4], bL1[4];
            ldsm4(aHiB + kof,            aH[0]);
            ldsm4(aHiB + 16 * A_PITCH + kof, aH[1]);
            ldsm4(aLoB + kof,            aL[0]);
            ldsm4(aLoB + 16 * A_PITCH + kof, aL[1]);
            ldsm4(bHiB0 + kof, bH0);
            ldsm4(bHiB1 + kof, bH1);
            ldsm4(bLoB0 + kof, bL0);
            ldsm4(bLoB1 + kof, bL1);

            uint32_t b0h[4] = {bH0[0], bH0[1], bH1[0], bH1[1]};
            uint32_t b1h[4] = {bH0[2], bH0[3], bH1[2], bH1[3]};
            uint32_t b0l[4] = {bL0[0], bL0[1], bL1[0], bL1[1]};
            uint32_t b1l[4] = {bL0[2], bL0[3], bL1[2], bL1[3]};

#pragma unroll
            for (int tm = 0; tm < 2; tm++) {
#pragma unroll
                for (int tn = 0; tn < 4; tn++) {
                    MMA16816(acc[tm][tn], aH[tm], b0h[tn], b1h[tn]);
                    MMA16816(acc[tm][tn], aH[tm], b0l[tn], b1l[tn]);
                    MMA16816(acc[tm][tn], aL[tm], b0h[tn], b1h[tn]);
                }
            }
        }
        __syncthreads();
    }

    const int g  = lane >> 2;
    const int t4 = lane & 3;
#pragma unroll
    for (int tm = 0; tm < 2; tm++) {
        int row0 = rowBase + wm * 32 + tm * 16 + g;
#pragma unroll
        for (int tn = 0; tn < 4; tn++) {
            int col = colBase + wn * 32 + tn * 8 + t4 * 2;
            if (col >= N) continue;
            float b0 = bias[col], b1 = bias[col + 1];
            float* cc = acc[tm][tn];
            float v00 = cc[0] + b0, v01 = cc[1] + b1;
            float v10 = cc[2] + b0, v11 = cc[3] + b1;
            if (RELU) {
                v00 = fmaxf(v00, 0.f); v01 = fmaxf(v01, 0.f);
                v10 = fmaxf(v10, 0.f); v11 = fmaxf(v11, 0.f);
            }
            if (OMODE == 0) {
                if (row0 < M)     *(float2*)(C + (size_t)row0 * N + col)     = make_float2(v00, v01);
                if (row0 + 8 < M) *(float2*)(C + (size_t)(row0 + 8) * N + col) = make_float2(v10, v11);
            } else {
                int head = col >> 5, wi = col & 31;
                if (row0 < M) {
                    int s = row0 >> 3, bb = row0 & 7;
                    *(float2*)(C + (((size_t)(bb * 8 + head)) * nrows + s) * 32 + wi) = make_float2(v00, v01);
                }
                if (row0 + 8 < M) {
                    int r1 = row0 + 8;
                    int s = r1 >> 3, bb = r1 & 7;
                    *(float2*)(C + (((size_t)(bb * 8 + head)) * nrows + s) * 32 + wi) = make_float2(v10, v11);
                }
            }
        }
    }
}

// ---------------- prep: K/V fp32 -> padded bf16 hi/lo (V transposed) ----------
__global__ void prep_kv(const float* __restrict__ k, const float* __restrict__ v,
                        __nv_bfloat16* __restrict__ kh, __nv_bfloat16* __restrict__ kl,
                        __nv_bfloat16* __restrict__ vh, __nv_bfloat16* __restrict__ vl)
{
    int idx = blockIdx.x * 256 + threadIdx.x;          // over 64 * 960 * 32
    if (idx >= 64 * NQP_ * 32) return;
    int ch  = idx & 31;
    int key = (idx >> 5) % NQP_;
    int bh  = idx / (NQP_ * 32);
    int tidx = (bh * 32 + ch) * NQP_ + key;
    if (key < NQ_) {
        int src = (bh * NQ_ + key) * 32 + ch;
        float kv = k[src];
        __nv_bfloat16 h = __float2bfloat16_rn(kv);
        kh[idx] = h;
        kl[idx] = __float2bfloat16_rn(kv - __bfloat162float(h));
        float vv = v[src];
        __nv_bfloat16 hv = __float2bfloat16_rn(vv);
        vh[tidx] = hv;
        vl[tidx] = __float2bfloat16_rn(vv - __bfloat162float(hv));
    } else {
        kh[idx] = __float2bfloat16_rn(0.f);
        kl[idx] = __float2bfloat16_rn(0.f);
        vh[tidx] = __float2bfloat16_rn(0.f);
        vl[tidx] = __float2bfloat16_rn(0.f);
    }
}

// ---------------- mma.sync flash self-attention -------------------------------
// 128 threads (4 warps), block = (64-query tile, bh). 3-term bf16 throughout.
#define KS_PITCH 80     // 64 rows x (32 bf16 + pad)
#define VS_PITCH 144    // 32 rows x (64 bf16 + pad)
__global__ void __launch_bounds__(128) attn_mma(
    const float* __restrict__ q,
    const __nv_bfloat16* __restrict__ kh, const __nv_bfloat16* __restrict__ kl,
    const __nv_bfloat16* __restrict__ vh, const __nv_bfloat16* __restrict__ vl,
    float* __restrict__ out)
{
    __shared__ __align__(16) char KsH[64 * KS_PITCH];
    __shared__ __align__(16) char KsL[64 * KS_PITCH];
    __shared__ __align__(16) char VsH[32 * VS_PITCH];
    __shared__ __align__(16) char VsL[32 * VS_PITCH];

    const int bh   = blockIdx.y;
    const int q0   = blockIdx.x * 64;
    const int tid  = threadIdx.x;
    const int lane = tid & 31;
    const int w    = tid >> 5;        // warp: query rows w*16..w*16+15
    const int g    = lane >> 2;
    const int t4   = lane & 3;
    const int laneRow  = lane & 15;
    const int laneHalf = (lane & 16) ? 16 : 0;

    const uint32_t sKH = su32(KsH), sKL = su32(KsL);
    const uint32_t sVH = su32(VsH), sVL = su32(VsL);
    const float scale = 0.17677669529663687f;   // 1/sqrt(32)

    // ---- stage Q (scaled, hi/lo) through KsH/KsL, load A fragments ----
#pragma unroll
    for (int i = 0; i < 8; i++) {
        int p = tid + i * 128;            // 1024 bf16x2 pairs
        int row = p >> 4, chp = p & 15;
        int gq = q0 + row;
        float a0 = 0.f, a1 = 0.f;
        if (gq < NQ_) {
            const float* src = q + ((size_t)bh * NQ_ + gq) * 32 + chp * 2;
            a0 = src[0] * scale; a1 = src[1] * scale;
        }
        float h0 = __bfloat162float(__float2bfloat16_rn(a0));
        float h1 = __bfloat162float(__float2bfloat16_rn(a1));
        *(uint32_t*)(KsH + row * KS_PITCH + chp * 4) = pk(h0, h1);
        *(uint32_t*)(KsL + row * KS_PITCH + chp * 4) = pk(a0 - h0, a1 - h1);
    }
    __syncthreads();

    uint32_t aQh[2][4], aQl[2][4];
#pragma unroll
    for (int kc = 0; kc < 2; kc++) {
        ldsm4(sKH + (w * 16 + laneRow) * KS_PITCH + laneHalf + kc * 32, aQh[kc]);
        ldsm4(sKL + (w * 16 + laneRow) * KS_PITCH + laneHalf + kc * 32, aQl[kc]);
    }
    __syncthreads();

    float sO[4][4];
#pragma unroll
    for (int tn = 0; tn < 4; tn++)
#pragma unroll
        for (int j = 0; j < 4; j++) sO[tn][j] = 0.f;
    float m0 = -1e30f, m1 = -1e30f, l0 = 0.f, l1 = 0.f;

    for (int kt = 0; kt < NQP_; kt += 64) {
        // ---- load K tile [64][32] hi/lo and V^T tile [32][64] hi/lo ----
#pragma unroll
        for (int i = 0; i < 2; i++) {
            int idx = tid + i * 128;               // 256 16B-slots
            int row = idx >> 2, seg = idx & 3;     // K: 64 rows x 4 segs
            const uint4* srcH = (const uint4*)(kh + ((size_t)bh * NQP_ + kt + row) * 32 + seg * 8);
            const uint4* srcL = (const uint4*)(kl + ((size_t)bh * NQP_ + kt + row) * 32 + seg * 8);
            *(uint4*)(KsH + row * KS_PITCH + seg * 16) = *srcH;
            *(uint4*)(KsL + row * KS_PITCH + seg * 16) = *srcL;
            int vrow = idx >> 3, vseg = idx & 7;   // V: 32 rows x 8 segs
            const uint4* vsrcH = (const uint4*)(vh + ((size_t)bh * 32 + vrow) * NQP_ + kt + vseg * 8);
            const uint4* vsrcL = (const uint4*)(vl + ((size_t)bh * 32 + vrow) * NQP_ + kt + vseg * 8);
            *(uint4*)(VsH + vrow * VS_PITCH + vseg * 16) = *vsrcH;
            *(uint4*)(VsL + vrow * VS_PITCH + vseg * 16) = *vsrcL;
        }
        __syncthreads();

        // ---- S = Q K^T (3-term) ----
        float sS[8][4];
#pragma unroll
        for (int tn = 0; tn < 8; tn++)
#pragma unroll
            for (int j = 0; j < 4; j++) sS[tn][j] = 0.f;

#pragma unroll
        for (int kc = 0; kc < 2; kc++) {
#pragma unroll
            for (int kg = 0; kg < 4; kg++) {       // 16-key groups
                uint32_t bKh[4], bKl[4];
                ldsm4(sKH + (kg * 16 + laneRow) * KS_PITCH + laneHalf + kc * 32, bKh);
                ldsm4(sKL + (kg * 16 + laneRow) * KS_PITCH + laneHalf + kc * 32, bKl);
                float* c0 = sS[kg * 2];
                float* c1 = sS[kg * 2 + 1];
                MMA16816(c0, aQh[kc], bKh[0], bKh[2]);
                MMA16816(c0, aQh[kc], bKl[0], bKl[2]);
                MMA16816(c0, aQl[kc], bKh[0], bKh[2]);
                MMA16816(c1, aQh[kc], bKh[1], bKh[3]);
                MMA16816(c1, aQh[kc], bKl[1], bKl[3]);
                MMA16816(c1, aQl[kc], bKh[1], bKh[3]);
            }
        }

        // ---- mask padded keys (last tile only) ----
        if (kt + 64 > NQ_) {
#pragma unroll
            for (int tn = 0; tn < 8; tn++) {
                int k0 = kt + tn * 8 + t4 * 2;
                if (k0 >= NQ_)     { sS[tn][0] = -1e30f; sS[tn][2] = -1e30f; }
                if (k0 + 1 >= NQ_) { sS[tn][1] = -1e30f; sS[tn][3] = -1e30f; }
            }
        }

        // ---- online softmax (rows g and g+8, quad reduction) ----
        float mx0 = -1e30f, mx1 = -1e30f;
#pragma unroll
        for (int tn = 0; tn < 8; tn++) {
            mx0 = fmaxf(mx0, fmaxf(sS[tn][0], sS[tn][1]));
            mx1 = fmaxf(mx1, fmaxf(sS[tn][2], sS[tn][3]));
        }
        mx0 = fmaxf(mx0, __shfl_xor_sync(0xffffffffu, mx0, 1));
        mx0 = fmaxf(mx0, __shfl_xor_sync(0xffffffffu, mx0, 2));
        mx1 = fmaxf(mx1, __shfl_xor_sync(0xffffffffu, mx1, 1));
        mx1 = fmaxf(mx1, __shfl_xor_sync(0xffffffffu, mx1, 2));
        float nm0 = fmaxf(m0, mx0), nm1 = fmaxf(m1, mx1);
        float cr0 = __expf(m0 - nm0), cr1 = __expf(m1 - nm1);
        m0 = nm0; m1 = nm1;
        float rs0 = 0.f, rs1 = 0.f;
#pragma unroll
        for (int tn = 0; tn < 8; tn++) {
            sS[tn][0] = __expf(sS[tn][0] - nm0);
            sS[tn][1] = __expf(sS[tn][1] - nm0);
            sS[tn][2] = __expf(sS[tn][2] - nm1);
            sS[tn][3] = __expf(sS[tn][3] - nm1);
            rs0 += sS[tn][0] + sS[tn][1];
            rs1 += sS[tn][2] + sS[tn][3];
        }
        rs0 += __shfl_xor_sync(0xffffffffu, rs0, 1);
        rs0 += __shfl_xor_sync(0xffffffffu, rs0, 2);
        rs1 += __shfl_xor_sync(0xffffffffu, rs1, 1);
        rs1 += __shfl_xor_sync(0xffffffffu, rs1, 2);
        l0 = l0 * cr0 + rs0;
        l1 = l1 * cr1 + rs1;
#pragma unroll
        for (int tn = 0; tn < 4; tn++) {
            sO[tn][0] *= cr0; sO[tn][1] *= cr0;
            sO[tn][2] *= cr1; sO[tn][3] *= cr1;
        }

        // ---- O += P V (P frags straight from registers, 3-term) ----
#pragma unroll
        for (int kc = 0; kc < 4; kc++) {           // key chunks of 16
            const float* cA = sS[kc * 2];
            const float* cB = sS[kc * 2 + 1];
            float hA0 = __bfloat162float(__float2bfloat16_rn(cA[0]));
            float hA1 = __bfloat162float(__float2bfloat16_rn(cA[1]));
            float hA2 = __bfloat162float(__float2bfloat16_rn(cA[2]));
            float hA3 = __bfloat162float(__float2bfloat16_rn(cA[3]));
            float hB0 = __bfloat162float(__float2bfloat16_rn(cB[0]));
            float hB1 = __bfloat162float(__float2bfloat16_rn(cB[1]));
            float hB2 = __bfloat162float(__float2bfloat16_rn(cB[2]));
            float hB3 = __bfloat162float(__float2bfloat16_rn(cB[3]));
            uint32_t pH[4] = { pk(hA0, hA1), pk(hA2, hA3), pk(hB0, hB1), pk(hB2, hB3) };
            uint32_t pL[4] = { pk(cA[0]-hA0, cA[1]-hA1), pk(cA[2]-hA2, cA[3]-hA3),
                               pk(cB[0]-hB0, cB[1]-hB1), pk(cB[2]-hB2, cB[3]-hB3) };
#pragma unroll
            for (int ng = 0; ng < 2; ng++) {       // channel groups of 16
                uint32_t bVh[4], bVl[4];
                ldsm4(sVH + (ng * 16 + laneRow) * VS_PITCH + laneHalf + kc * 32, bVh);
                ldsm4(sVL + (ng * 16 + laneRow) * VS_PITCH + laneHalf + kc * 32, bVl);
                float* o0 = sO[ng * 2];
                float* o1 = sO[ng * 2 + 1];
                MMA16816(o0, pH, bVh[0], bVh[2]);
                MMA16816(o0, pH, bVl[0], bVl[2]);
                MMA16816(o0, pL, bVh[0], bVh[2]);
                MMA16816(o1, pH, bVh[1], bVh[3]);
                MMA16816(o1, pH, bVl[1], bVl[3]);
                MMA16816(o1, pL, bVh[1], bVh[3]);
            }
        }
        __syncthreads();
    }

    // ---- epilogue ----
    const int b = bh >> 3, h = bh & 7;
    float inv0 = 1.f / l0, inv1 = 1.f / l1;
    int r0 = q0 + w * 16 + g;
    int r1 = r0 + 8;
#pragma unroll
    for (int tn = 0; tn < 4; tn++) {
        int col = h * 32 + tn * 8 + t4 * 2;
        if (r0 < NQ_)
            *(float2*)(out + ((size_t)r0 * B_ + b) * D_ + col) =
                make_float2(sO[tn][0] * inv0, sO[tn][1] * inv0);
        if (r1 < NQ_)
            *(float2*)(out + ((size_t)r1 * B_ + b) * D_ + col) =
                make_float2(sO[tn][2] * inv1, sO[tn][3] * inv1);
    }
}

// ---------------- layer norm ----------------
__global__ void ln_kernel(const float* __restrict__ a, const float* __restrict__ r,
                          const float* __restrict__ g, const float* __restrict__ be,
                          float* __restrict__ out)
{
    __shared__ float red[32];
    const int t = blockIdx.x, i = threadIdx.x;
    float x = a[(size_t)t * D_ + i] + r[(size_t)t * D_ + i];

    float s = x;
#pragma unroll
    for (int o = 16; o; o >>= 1) s += __shfl_xor_sync(0xffffffffu, s, o);
    if ((i & 31) == 0) red[i >> 5] = s;
    __syncthreads();
    if (i < 8) {
        float vv = red[i];
#pragma unroll
        for (int o = 4; o; o >>= 1) vv += __shfl_xor_sync(0xffu, vv, o);
        if (i == 0) red[0] = vv;
    }
    __syncthreads();
    float mean = red[0] * (1.f / 256.f);
    float d = x - mean;
    float s2 = d * d;
#pragma unroll
    for (int o = 16; o; o >>= 1) s2 += __shfl_xor_sync(0xffffffffu, s2, o);
    __syncthreads();
    if ((i & 31) == 0) red[i >> 5] = s2;
    __syncthreads();
    if (i < 8) {
        float vv = red[i];
#pragma unroll
        for (int o = 4; o; o >>= 1) vv += __shfl_xor_sync(0xffu, vv, o);
        if (i == 0) red[0] = vv;
    }
    __syncthreads();
    float var = red[0] * (1.f / 256.f);
    out[(size_t)t * D_ + i] = d * rsqrtf(var + 1e-5f) * g[i] + be[i];
}

// ---------------- deformable sampling ----------------
__global__ void sample_kernel(const float* __restrict__ off, const float* __restrict__ awl,
                              const float* __restrict__ refp, const float* __restrict__ val,
                              float* __restrict__ out)
{
    const int gw   = blockIdx.x * 8 + (threadIdx.x >> 5);
    const int lane = threadIdx.x & 31;
    const int t = gw >> 3;
    const int h = gw & 7;
    const int b = t & 7;

    float logit = (lane < 20) ? awl[(size_t)t * 160 + h * 20 + lane] : -1e30f;
    float mx = logit;
#pragma unroll
    for (int o = 16; o; o >>= 1) mx = fmaxf(mx, __shfl_xor_sync(0xffffffffu, mx, o));
    float e = (lane < 20) ? __expf(logit - mx) : 0.f;
    float sm = e;
#pragma unroll
    for (int o = 16; o; o >>= 1) sm += __shfl_xor_sync(0xffffffffu, sm, o);
    float pw = e / sm;

    const float* rp = refp + (size_t)t * 16;
    const float* op = off + (size_t)t * 320 + h * 40;

    float acc = 0.f;
#pragma unroll
    for (int l = 0; l < 4; l++) {
        const int Wl = c_Hl[l];
        const int Hl = c_Hl[l];
        const float r0 = rp[l * 4 + 0], r1 = rp[l * 4 + 1];
        const float r2 = rp[l * 4 + 2], r3 = rp[l * 4 + 3];
        const float* vbase = val + ((size_t)(b * 8 + h) * S_ + c_start[l]) * 32;
#pragma unroll
        for (int p = 0; p < 5; p++) {
            float aw = __shfl_sync(0xffffffffu, pw, l * 5 + p);
            float ox = op[(l * 5 + p) * 2 + 0];
            float oy = op[(l * 5 + p) * 2 + 1];
            float x = (r0 + ox * 0.2f * r2 * 0.5f) * (float)Wl - 0.5f;
            float y = (r1 + oy * 0.2f * r3 * 0.5f) * (float)Hl - 0.5f;
            float x0f = floorf(x), y0f = floorf(y);
            float fx = x - x0f, fy = y - y0f;
            int x0 = (int)x0f, y0 = (int)y0f;
#pragma unroll
            for (int dy = 0; dy < 2; dy++) {
#pragma unroll
                for (int dx = 0; dx < 2; dx++) {
                    int xi = x0 + dx, yi = y0 + dy;
                    float w = (dx ? fx : 1.f - fx) * (dy ? fy : 1.f - fy);
                    bool valid = (xi >= 0) && (xi < Wl) && (yi >= 0) && (yi < Hl);
                    if (valid && w != 0.f)
                        acc = fmaf(aw * w, vbase[((size_t)yi * Wl + xi) * 32 + lane], acc);
                }
            }
        }
    }
    out[(size_t)t * D_ + h * 32 + lane] = acc;
}

// ---------------- host launcher ----------------
static inline int cdiv(int a, int b) { return (a + b - 1) / b; }

extern "C" void kernel_launch(void* const* d_in, const int* in_sizes, int n_in,
                              void* d_out, int out_size)
{
    const float* tgt     = (const float*)d_in[0];
    const float* pos     = (const float*)d_in[1];
    const float* refp    = (const float*)d_in[2];
    const float* memory  = (const float*)d_in[3];
    const float* sa_in_w = (const float*)d_in[4];
    const float* sa_in_b = (const float*)d_in[5];
    const float* sa_out_w= (const float*)d_in[6];
    const float* sa_out_b= (const float*)d_in[7];
    const float* off_w   = (const float*)d_in[8];
    const float* off_b   = (const float*)d_in[9];
    const float* aw_w    = (const float*)d_in[10];
    const float* aw_b    = (const float*)d_in[11];
    const float* val_w   = (const float*)d_in[12];
    const float* val_b   = (const float*)d_in[13];
    const float* co_w    = (const float*)d_in[14];
    const float* co_b    = (const float*)d_in[15];
    const float* w1      = (const float*)d_in[16];
    const float* b1      = (const float*)d_in[17];
    const float* w2      = (const float*)d_in[18];
    const float* b2      = (const float*)d_in[19];
    const float* ln1_g   = (const float*)d_in[20];
    const float* ln1_b   = (const float*)d_in[21];
    const float* ln2_g   = (const float*)d_in[22];
    const float* ln2_b   = (const float*)d_in[23];
    const float* ln3_g   = (const float*)d_in[24];
    const float* ln3_b   = (const float*)d_in[25];
    float* out = (float*)d_out;

    void *p;
    cudaGetSymbolAddress(&p, g_q);      float* q_     = (float*)p;
    cudaGetSymbolAddress(&p, g_k);      float* k_     = (float*)p;
    cudaGetSymbolAddress(&p, g_v);      float* v_     = (float*)p;
    cudaGetSymbolAddress(&p, g_kh);     __nv_bfloat16* kh_ = (__nv_bfloat16*)p;
    cudaGetSymbolAddress(&p, g_kl);     __nv_bfloat16* kl_ = (__nv_bfloat16*)p;
    cudaGetSymbolAddress(&p, g_vh);     __nv_bfloat16* vh_ = (__nv_bfloat16*)p;
    cudaGetSymbolAddress(&p, g_vl);     __nv_bfloat16* vl_ = (__nv_bfloat16*)p;
    cudaGetSymbolAddress(&p, g_attn);   float* attn_  = (float*)p;
    cudaGetSymbolAddress(&p, g_saproj); float* sap_   = (float*)p;
    cudaGetSymbolAddress(&p, g_tgt1);   float* tgt1_  = (float*)p;
    cudaGetSymbolAddress(&p, g_value);  float* value_ = (float*)p;
    cudaGetSymbolAddress(&p, g_off);    float* off_   = (float*)p;
    cudaGetSymbolAddress(&p, g_aw);     float* aw_    = (float*)p;
    cudaGetSymbolAddress(&p, g_ca);     float* ca_    = (float*)p;
    cudaGetSymbolAddress(&p, g_caproj); float* cap_   = (float*)p;
    cudaGetSymbolAddress(&p, g_tgt2);   float* tgt2_  = (float*)p;
    cudaGetSymbolAddress(&p, g_ffh);    float* ffh_   = (float*)p;
    cudaGetSymbolAddress(&p, g_ff);     float* ff_    = (float*)p;

    static bool attr_done = false;
    if (!attr_done) {
        cudaFuncSetAttribute(tgemm<1,1,false>, cudaFuncAttributeMaxDynamicSharedMemorySize, SM_TOTAL);
        cudaFuncSetAttribute(tgemm<0,1,false>, cudaFuncAttributeMaxDynamicSharedMemorySize, SM_TOTAL);
        cudaFuncSetAttribute(tgemm<0,0,false>, cudaFuncAttributeMaxDynamicSharedMemorySize, SM_TOTAL);
        cudaFuncSetAttribute(tgemm<1,0,false>, cudaFuncAttributeMaxDynamicSharedMemorySize, SM_TOTAL);
        cudaFuncSetAttribute(tgemm<0,0,true >, cudaFuncAttributeMaxDynamicSharedMemorySize, SM_TOTAL);
        attr_done = true;
    }

    const dim3 blk(256);
    const int mt = cdiv(NTOK_, 128);   // 57

    // ---- self-attention ----
    tgemm<1,1,false><<<dim3(4, mt), 256, SM_TOTAL>>>(tgt, pos, sa_in_w,           sa_in_b,       q_, NTOK_, 256, 256, NQ_);
    tgemm<1,1,false><<<dim3(4, mt), 256, SM_TOTAL>>>(tgt, pos, sa_in_w + 256*256, sa_in_b + 256, k_, NTOK_, 256, 256, NQ_);
    tgemm<0,1,false><<<dim3(4, mt), 256, SM_TOTAL>>>(tgt, nullptr, sa_in_w + 512*256, sa_in_b + 512, v_, NTOK_, 256, 256, NQ_);
    prep_kv<<<cdiv(64 * NQP_ * 32, 256), 256>>>(k_, v_, kh_, kl_, vh_, vl_);
    attn_mma<<<dim3(cdiv(NQ_, 64), B_ * H_), 128>>>(q_, kh_, kl_, vh_, vl_, attn_);
    tgemm<0,0,false><<<dim3(4, mt), 256, SM_TOTAL>>>(attn_, nullptr, sa_out_w, sa_out_b, sap_, NTOK_, 256, 256, 0);
    ln_kernel<<<NTOK_, blk>>>(tgt, sap_, ln2_g, ln2_b, tgt1_);

    // ---- deformable cross-attention ----
    tgemm<0,1,false><<<dim3(4, cdiv(MTOK_,128)), 256, SM_TOTAL>>>(memory, nullptr, val_w, val_b, value_, MTOK_, 256, 256, S_);
    tgemm<1,0,false><<<dim3(5, mt), 256, SM_TOTAL>>>(tgt1_, pos, off_w, off_b, off_, NTOK_, 320, 256, 0);
    tgemm<1,0,false><<<dim3(3, mt), 256, SM_TOTAL>>>(tgt1_, pos, aw_w, aw_b, aw_, NTOK_, 160, 256, 0);
    sample_kernel<<<NTOK_ * H_ / 8, blk>>>(off_, aw_, refp, value_, ca_);
    tgemm<0,0,false><<<dim3(4, mt), 256, SM_TOTAL>>>(ca_, nullptr, co_w, co_b, cap_, NTOK_, 256, 256, 0);
    ln_kernel<<<NTOK_, blk>>>(tgt1_, cap_, ln1_g, ln1_b, tgt2_);

    // ---- FFN ----
    tgemm<0,0,true ><<<dim3(16, mt), 256, SM_TOTAL>>>(tgt2_, nullptr, w1, b1, ffh_, NTOK_, DFF_, 256, 0);
    tgemm<0,0,false><<<dim3(4, mt), 256, SM_TOTAL>>>(ffh_, nullptr, w2, b2, ff_, NTOK_, 256, DFF_, 0);
    ln_kernel<<<NTOK_, blk>>>(tgt2_, ff_, ln3_g, ln3_b, out);
}